// round 1
// baseline (speedup 1.0000x reference)
#include <cuda_runtime.h>
#include <math.h>

#define S_LEN 2048
#define HIDDEN 2048
#define NH 16
#define NKV 2
#define HD 128
#define QDIM (NH*HD)    // 2048
#define KVDIM (NKV*HD)  // 256
#define NREP (NH/NKV)   // 8

// Scratch (device globals; no allocation allowed)
__device__ float g_q[S_LEN * QDIM];
__device__ float g_k[S_LEN * KVDIM];
__device__ float g_v[S_LEN * KVDIM];
__device__ float g_att[S_LEN * QDIM];

// ---------------------------------------------------------------------------
// SGEMM: C[M,N] = A[M,K] @ B[K,N] (+ bias). 128x128 tile, BK=8, 256 threads,
// 8x8 microtile split into 4x 4-wide fragments (rows ty*4 / 64+ty*4, cols
// tx*4 / 64+tx*4) for conflict-free LDS.128.
// Requires M%128==0, N%128==0, K%8==0 (true here: 2048/2048/256).
// ---------------------------------------------------------------------------
__global__ __launch_bounds__(256) void sgemm128(
    const float* __restrict__ A, const float* __restrict__ B,
    const float* __restrict__ bias, float* __restrict__ C,
    int M, int N, int K)
{
    __shared__ float As[8][132];   // transposed A tile, padded
    __shared__ float Bs[8][132];

    const int tid = threadIdx.x;
    const int tx = tid & 15, ty = tid >> 4;
    const int row0 = blockIdx.y * 128;
    const int col0 = blockIdx.x * 128;

    // Global load mapping
    const int a_row = tid >> 1;            // 0..127
    const int a_col = (tid & 1) * 4;       // 0 or 4
    const int b_row = tid >> 5;            // 0..7
    const int b_col = (tid & 31) * 4;      // 0..124

    const float* Aptr = A + (size_t)(row0 + a_row) * K + a_col;
    const float* Bptr = B + (size_t)b_row * N + col0 + b_col;

    float acc[8][8];
    #pragma unroll
    for (int i = 0; i < 8; i++)
        #pragma unroll
        for (int j = 0; j < 8; j++) acc[i][j] = 0.f;

    for (int k0 = 0; k0 < K; k0 += 8) {
        float4 av = *(const float4*)(Aptr + k0);
        float4 bv = *(const float4*)(Bptr + (size_t)k0 * N);
        __syncthreads();
        As[a_col + 0][a_row] = av.x;
        As[a_col + 1][a_row] = av.y;
        As[a_col + 2][a_row] = av.z;
        As[a_col + 3][a_row] = av.w;
        *(float4*)&Bs[b_row][b_col] = bv;
        __syncthreads();

        #pragma unroll
        for (int kk = 0; kk < 8; kk++) {
            float a[8], b[8];
            *(float4*)(a)     = *(const float4*)&As[kk][ty * 4];
            *(float4*)(a + 4) = *(const float4*)&As[kk][64 + ty * 4];
            *(float4*)(b)     = *(const float4*)&Bs[kk][tx * 4];
            *(float4*)(b + 4) = *(const float4*)&Bs[kk][64 + tx * 4];
            #pragma unroll
            for (int i = 0; i < 8; i++)
                #pragma unroll
                for (int j = 0; j < 8; j++)
                    acc[i][j] = fmaf(a[i], b[j], acc[i][j]);
        }
    }

    // Epilogue
    #pragma unroll
    for (int half = 0; half < 2; half++) {
        int cb = col0 + half * 64 + tx * 4;
        float4 bb = make_float4(0.f, 0.f, 0.f, 0.f);
        if (bias) bb = *(const float4*)(bias + cb);
        #pragma unroll
        for (int ii = 0; ii < 8; ii++) {
            int r = row0 + ((ii < 4) ? (ty * 4 + ii) : (64 + ty * 4 + ii - 4));
            float4 res;
            res.x = acc[ii][half * 4 + 0] + bb.x;
            res.y = acc[ii][half * 4 + 1] + bb.y;
            res.z = acc[ii][half * 4 + 2] + bb.z;
            res.w = acc[ii][half * 4 + 3] + bb.w;
            *(float4*)(C + (size_t)r * N + cb) = res;
        }
    }
}

// ---------------------------------------------------------------------------
// RoPE (in-place). x layout: [S, nheads*128]. cos/sin: [S, 128].
// For d<64:  x'[d]    = x[d]*cos[d]      - x[d+64]*sin[d]
//            x'[d+64] = x[d+64]*cos[d+64] + x[d]*sin[d+64]
// ---------------------------------------------------------------------------
__global__ void rope_kernel(float* __restrict__ x,
                            const float* __restrict__ cosp,
                            const float* __restrict__ sinp,
                            int nheads)
{
    int idx = blockIdx.x * blockDim.x + threadIdx.x;
    int total = S_LEN * nheads * 64;
    if (idx >= total) return;
    int d = idx & 63;
    int t = idx >> 6;
    int hh = t % nheads;
    int s = t / nheads;
    size_t base = (size_t)s * nheads * HD + hh * HD;
    float x1 = x[base + d];
    float x2 = x[base + d + 64];
    float c1 = cosp[s * HD + d],      s1 = sinp[s * HD + d];
    float c2 = cosp[s * HD + d + 64], s2 = sinp[s * HD + d + 64];
    x[base + d]      = x1 * c1 - x2 * s1;
    x[base + d + 64] = x2 * c2 + x1 * s2;
}

// ---------------------------------------------------------------------------
// Flash attention fp32, causal, GQA. One CTA = one (q-block of 64 rows, head).
// 256 threads (tx 0..15, ty 0..15). Score cols owned: tx+16j; rows: ty+16i.
// Smem: Qs/Ks/Vs 64x132 (padded), Ps 64x68. Online softmax.
// ---------------------------------------------------------------------------
__global__ __launch_bounds__(256) void flash_attn(
    const float* __restrict__ Q, const float* __restrict__ Kp,
    const float* __restrict__ Vp, float* __restrict__ O)
{
    extern __shared__ float sm[];
    float* Qs = sm;                 // 64*132
    float* Ks = Qs + 64 * 132;      // 64*132
    float* Vs = Ks + 64 * 132;      // 64*132
    float* Ps = Vs + 64 * 132;      // 64*68

    const int qb = gridDim.x - 1 - blockIdx.x;   // heavy blocks first
    const int h = blockIdx.y;
    const int kvh = h / NREP;
    const int tid = threadIdx.x;
    const int tx = tid & 15, ty = tid >> 4;
    const int q0 = qb * 64;
    const float scale = 0.08838834764831845f;    // 1/sqrt(128)

    // Load Q tile [64 x 128]
    for (int i = tid; i < 64 * 32; i += 256) {
        int r = i >> 5, c4 = (i & 31) * 4;
        *(float4*)(Qs + r * 132 + c4) =
            *(const float4*)(Q + (size_t)(q0 + r) * QDIM + h * HD + c4);
    }

    float m_i[4], l_i[4];
    float o[4][8];
    #pragma unroll
    for (int i = 0; i < 4; i++) {
        m_i[i] = -INFINITY; l_i[i] = 0.f;
        #pragma unroll
        for (int j = 0; j < 8; j++) o[i][j] = 0.f;
    }

    for (int kb = 0; kb <= qb; kb++) {
        const int k0 = kb * 64;
        __syncthreads();  // prev iter done reading Ks/Vs/Ps; Q visible (iter 0)
        for (int i = tid; i < 64 * 32; i += 256) {
            int r = i >> 5, c4 = (i & 31) * 4;
            size_t goff = (size_t)(k0 + r) * KVDIM + kvh * HD + c4;
            *(float4*)(Ks + r * 132 + c4) = *(const float4*)(Kp + goff);
            *(float4*)(Vs + r * 132 + c4) = *(const float4*)(Vp + goff);
        }
        __syncthreads();

        // S = Q K^T, rows ty+16i, cols tx+16j
        float s[4][4];
        #pragma unroll
        for (int i = 0; i < 4; i++)
            #pragma unroll
            for (int j = 0; j < 4; j++) s[i][j] = 0.f;

        for (int d = 0; d < 128; d += 4) {
            float4 qv[4], kv[4];
            #pragma unroll
            for (int i = 0; i < 4; i++)
                qv[i] = *(const float4*)(Qs + (ty + 16 * i) * 132 + d);
            #pragma unroll
            for (int j = 0; j < 4; j++)
                kv[j] = *(const float4*)(Ks + (tx + 16 * j) * 132 + d);
            #pragma unroll
            for (int i = 0; i < 4; i++)
                #pragma unroll
                for (int j = 0; j < 4; j++) {
                    s[i][j] = fmaf(qv[i].x, kv[j].x, s[i][j]);
                    s[i][j] = fmaf(qv[i].y, kv[j].y, s[i][j]);
                    s[i][j] = fmaf(qv[i].z, kv[j].z, s[i][j]);
                    s[i][j] = fmaf(qv[i].w, kv[j].w, s[i][j]);
                }
        }

        // scale + causal mask (diagonal block only)
        #pragma unroll
        for (int i = 0; i < 4; i++) {
            int rg = q0 + ty + 16 * i;
            #pragma unroll
            for (int j = 0; j < 4; j++) {
                int cg = k0 + tx + 16 * j;
                s[i][j] = (cg > rg) ? -INFINITY : s[i][j] * scale;
            }
        }

        // online softmax per row
        #pragma unroll
        for (int i = 0; i < 4; i++) {
            float tmax = fmaxf(fmaxf(s[i][0], s[i][1]), fmaxf(s[i][2], s[i][3]));
            #pragma unroll
            for (int off = 1; off < 16; off <<= 1)
                tmax = fmaxf(tmax, __shfl_xor_sync(0xffffffffu, tmax, off));
            float m_new = fmaxf(m_i[i], tmax);
            float p0 = __expf(s[i][0] - m_new);
            float p1 = __expf(s[i][1] - m_new);
            float p2 = __expf(s[i][2] - m_new);
            float p3 = __expf(s[i][3] - m_new);
            float tsum = p0 + p1 + p2 + p3;
            #pragma unroll
            for (int off = 1; off < 16; off <<= 1)
                tsum += __shfl_xor_sync(0xffffffffu, tsum, off);
            float alpha = __expf(m_i[i] - m_new);
            l_i[i] = l_i[i] * alpha + tsum;
            m_i[i] = m_new;
            #pragma unroll
            for (int j = 0; j < 8; j++) o[i][j] *= alpha;
            int r = ty + 16 * i;
            Ps[r * 68 + tx + 0]  = p0;
            Ps[r * 68 + tx + 16] = p1;
            Ps[r * 68 + tx + 32] = p2;
            Ps[r * 68 + tx + 48] = p3;
        }
        __syncthreads();

        // O += P @ V : rows ty+16i, cols tx*4 and 64+tx*4
        for (int jj = 0; jj < 64; jj++) {
            float4 va = *(const float4*)(Vs + jj * 132 + tx * 4);
            float4 vb = *(const float4*)(Vs + jj * 132 + 64 + tx * 4);
            #pragma unroll
            for (int i = 0; i < 4; i++) {
                float p = Ps[(ty + 16 * i) * 68 + jj];
                o[i][0] = fmaf(p, va.x, o[i][0]);
                o[i][1] = fmaf(p, va.y, o[i][1]);
                o[i][2] = fmaf(p, va.z, o[i][2]);
                o[i][3] = fmaf(p, va.w, o[i][3]);
                o[i][4] = fmaf(p, vb.x, o[i][4]);
                o[i][5] = fmaf(p, vb.y, o[i][5]);
                o[i][6] = fmaf(p, vb.z, o[i][6]);
                o[i][7] = fmaf(p, vb.w, o[i][7]);
            }
        }
    }

    // epilogue: O /= l, store to [s, h*128 + d]
    #pragma unroll
    for (int i = 0; i < 4; i++) {
        float inv = 1.f / l_i[i];
        int r = q0 + ty + 16 * i;
        float4 ra, rb;
        ra.x = o[i][0] * inv; ra.y = o[i][1] * inv;
        ra.z = o[i][2] * inv; ra.w = o[i][3] * inv;
        rb.x = o[i][4] * inv; rb.y = o[i][5] * inv;
        rb.z = o[i][6] * inv; rb.w = o[i][7] * inv;
        *(float4*)(O + (size_t)r * QDIM + h * HD + tx * 4) = ra;
        *(float4*)(O + (size_t)r * QDIM + h * HD + 64 + tx * 4) = rb;
    }
}

// ---------------------------------------------------------------------------
extern "C" void kernel_launch(void* const* d_in, const int* in_sizes, int n_in,
                              void* d_out, int out_size)
{
    const float* X    = (const float*)d_in[0];
    const float* cosp = (const float*)d_in[1];
    const float* sinp = (const float*)d_in[2];
    // d_in[3] = attention_mask (always causal; applied analytically)
    const float* Wq = (const float*)d_in[4];
    const float* bq = (const float*)d_in[5];
    const float* Wk = (const float*)d_in[6];
    const float* bk = (const float*)d_in[7];
    const float* Wv = (const float*)d_in[8];
    const float* bv = (const float*)d_in[9];
    const float* Wo = (const float*)d_in[10];
    float* out = (float*)d_out;

    float *q, *k, *v, *att;
    cudaGetSymbolAddress((void**)&q, g_q);
    cudaGetSymbolAddress((void**)&k, g_k);
    cudaGetSymbolAddress((void**)&v, g_v);
    cudaGetSymbolAddress((void**)&att, g_att);

    // QKV projections
    sgemm128<<<dim3(QDIM / 128, S_LEN / 128), 256>>>(X, Wq, bq, q, S_LEN, QDIM, HIDDEN);
    sgemm128<<<dim3(KVDIM / 128, S_LEN / 128), 256>>>(X, Wk, bk, k, S_LEN, KVDIM, HIDDEN);
    sgemm128<<<dim3(KVDIM / 128, S_LEN / 128), 256>>>(X, Wv, bv, v, S_LEN, KVDIM, HIDDEN);

    // RoPE on q and k
    rope_kernel<<<(S_LEN * NH * 64 + 255) / 256, 256>>>(q, cosp, sinp, NH);
    rope_kernel<<<(S_LEN * NKV * 64 + 255) / 256, 256>>>(k, cosp, sinp, NKV);

    // Flash attention
    size_t smem = (size_t)(3 * 64 * 132 + 64 * 68) * sizeof(float);
    cudaFuncSetAttribute(flash_attn, cudaFuncAttributeMaxDynamicSharedMemorySize, (int)smem);
    flash_attn<<<dim3(S_LEN / 64, NH), 256, smem>>>(q, k, v, att);

    // Output projection -> d_out
    sgemm128<<<dim3(QDIM / 128, S_LEN / 128), 256>>>(att, Wo, nullptr, out, S_LEN, QDIM, HIDDEN);
}

// round 3
// speedup vs baseline: 1.8840x; 1.8840x over previous
#include <cuda_runtime.h>
#include <math.h>
#include <stdint.h>

#define S_LEN 2048
#define HIDDEN 2048
#define NH 16
#define NKV 2
#define HD 128
#define QDIM (NH*HD)    // 2048
#define KVDIM (NKV*HD)  // 256
#define NREP (NH/NKV)   // 8

// Scratch (device globals; no allocation allowed)
__device__ float g_q[S_LEN * QDIM];
__device__ float g_k[S_LEN * KVDIM];
__device__ float g_v[S_LEN * KVDIM];
__device__ float g_att[S_LEN * QDIM];

// ===========================================================================
// helpers
// ===========================================================================
__device__ __forceinline__ uint32_t smem_to_u32(const void* p) {
    uint32_t a;
    asm("{ .reg .u64 t; cvta.to.shared.u64 t, %1; cvt.u32.u64 %0, t; }" : "=r"(a) : "l"(p));
    return a;
}
__device__ __forceinline__ uint32_t f2tf32(float f) {
    uint32_t r;
    asm("cvt.rna.tf32.f32 %0, %1;" : "=r"(r) : "f"(f));
    return r;
}
__device__ __forceinline__ void sts128u(uint32_t a, uint32_t x, uint32_t y, uint32_t z, uint32_t w) {
    asm volatile("st.shared.v4.b32 [%0], {%1,%2,%3,%4};" :: "r"(a), "r"(x), "r"(y), "r"(z), "r"(w) : "memory");
}
__device__ __forceinline__ uint32_t ldsu(uint32_t a) {
    uint32_t v; asm volatile("ld.shared.b32 %0, [%1];" : "=r"(v) : "r"(a)); return v;
}
__device__ __forceinline__ void mma_tf32(float* d, const uint32_t* a, const uint32_t* b) {
    asm volatile("mma.sync.aligned.m16n8k8.row.col.f32.tf32.tf32.f32 "
                 "{%0,%1,%2,%3}, {%4,%5,%6,%7}, {%8,%9}, {%0,%1,%2,%3};"
                 : "+f"(d[0]), "+f"(d[1]), "+f"(d[2]), "+f"(d[3])
                 : "r"(a[0]), "r"(a[1]), "r"(a[2]), "r"(a[3]), "r"(b[0]), "r"(b[1]));
}

// ===========================================================================
// tf32 mma.sync GEMM: C[M,N] = A[M,K] @ W[K,N] (+bias).
// CTA 128x128, BK=32, 256 threads (warp grid 2m x 4n, warp tile 64x32).
// As[m][k] stride 36 floats; Bs[k][n] stride 136 floats. Double buffered,
// register prefetch one chunk ahead. Requires M%128==0, N%128==0, K%32==0.
// ===========================================================================
#define AS_STRIDE 36
#define BS_STRIDE 136
#define AS_BYTES (128 * AS_STRIDE * 4)     // 18432
#define BS_BYTES (32 * BS_STRIDE * 4)      // 17408
#define GEMM_SMEM (2 * (AS_BYTES + BS_BYTES))  // 71680

__global__ __launch_bounds__(256) void tcgemm_tf32(
    const float* __restrict__ A, const float* __restrict__ W,
    const float* __restrict__ bias, float* __restrict__ C,
    int M, int N, int K)
{
    extern __shared__ float sm[];
    const uint32_t smb = smem_to_u32(sm);
    const uint32_t ASb[2] = { smb, smb + AS_BYTES };
    const uint32_t BSb[2] = { smb + 2 * AS_BYTES, smb + 2 * AS_BYTES + BS_BYTES };

    const int tid = threadIdx.x;
    const int lane = tid & 31, wid = tid >> 5;
    const int wm = wid & 1, wn = wid >> 1;        // 2 x 4 warp grid
    const int r1 = lane >> 2, cc = lane & 3;
    const int row0 = blockIdx.y * 128, col0 = blockIdx.x * 128;
    const int NC = K >> 5;

    // global-load mappings
    const int am = tid >> 3;        // A rows: am + 32t
    const int kq = tid & 7;         // A float4 index within 32-k chunk
    const int bk = tid >> 5;        // B rows: bk + 8t
    const int nq = tid & 31;        // B float4 index within 128-n

    float acc[4][4][4];
    #pragma unroll
    for (int mt = 0; mt < 4; mt++)
        #pragma unroll
        for (int nt = 0; nt < 4; nt++)
            #pragma unroll
            for (int i = 0; i < 4; i++) acc[mt][nt][i] = 0.f;

    float4 pa[4], pb[4];

    #define LDG_CHUNK(c) do { \
        _Pragma("unroll") \
        for (int t = 0; t < 4; t++) \
            pa[t] = *(const float4*)(A + (size_t)(row0 + am + 32 * t) * K + (c) * 32 + kq * 4); \
        _Pragma("unroll") \
        for (int t = 0; t < 4; t++) \
            pb[t] = *(const float4*)(W + (size_t)((c) * 32 + bk + 8 * t) * N + col0 + nq * 4); \
    } while (0)

    #define STS_CHUNK(buf) do { \
        _Pragma("unroll") \
        for (int t = 0; t < 4; t++) { \
            uint32_t ad = ASb[buf] + (uint32_t)(((am + 32 * t) * AS_STRIDE + kq * 4) * 4); \
            sts128u(ad, f2tf32(pa[t].x), f2tf32(pa[t].y), f2tf32(pa[t].z), f2tf32(pa[t].w)); \
        } \
        _Pragma("unroll") \
        for (int t = 0; t < 4; t++) { \
            uint32_t bd = BSb[buf] + (uint32_t)(((bk + 8 * t) * BS_STRIDE + nq * 4) * 4); \
            sts128u(bd, f2tf32(pb[t].x), f2tf32(pb[t].y), f2tf32(pb[t].z), f2tf32(pb[t].w)); \
        } \
    } while (0)

    LDG_CHUNK(0);
    STS_CHUNK(0);
    __syncthreads();

    for (int c = 0; c < NC; c++) {
        const int cur = c & 1;
        if (c + 1 < NC) LDG_CHUNK(c + 1);

        // compute from buffer cur
        const uint32_t AS = ASb[cur], BS = BSb[cur];
        #pragma unroll
        for (int ks = 0; ks < 4; ks++) {
            uint32_t afr[4][4], bfr[4][2];
            #pragma unroll
            for (int mt = 0; mt < 4; mt++) {
                uint32_t base = AS + (uint32_t)((((wm * 64 + mt * 16 + r1) * AS_STRIDE) + ks * 8 + cc) * 4);
                afr[mt][0] = ldsu(base);
                afr[mt][1] = ldsu(base + 8 * AS_STRIDE * 4);
                afr[mt][2] = ldsu(base + 16);
                afr[mt][3] = ldsu(base + 8 * AS_STRIDE * 4 + 16);
            }
            #pragma unroll
            for (int nt = 0; nt < 4; nt++) {
                uint32_t nb = BS + (uint32_t)((((ks * 8 + cc) * BS_STRIDE) + wn * 32 + nt * 8 + r1) * 4);
                bfr[nt][0] = ldsu(nb);
                bfr[nt][1] = ldsu(nb + 4 * BS_STRIDE * 4);
            }
            #pragma unroll
            for (int mt = 0; mt < 4; mt++)
                #pragma unroll
                for (int nt = 0; nt < 4; nt++)
                    mma_tf32(acc[mt][nt], afr[mt], bfr[nt]);
        }

        if (c + 1 < NC) STS_CHUNK((c + 1) & 1);
        __syncthreads();
    }

    // epilogue: direct float2 stores + bias
    #pragma unroll
    for (int mt = 0; mt < 4; mt++) {
        int r = row0 + wm * 64 + mt * 16 + r1;
        #pragma unroll
        for (int nt = 0; nt < 4; nt++) {
            int col = col0 + wn * 32 + nt * 8 + 2 * cc;
            float bx = 0.f, by = 0.f;
            if (bias) { bx = bias[col]; by = bias[col + 1]; }
            float2 v0, v1;
            v0.x = acc[mt][nt][0] + bx; v0.y = acc[mt][nt][1] + by;
            v1.x = acc[mt][nt][2] + bx; v1.y = acc[mt][nt][3] + by;
            *(float2*)(C + (size_t)r * N + col) = v0;
            *(float2*)(C + (size_t)(r + 8) * N + col) = v1;
        }
    }
    #undef LDG_CHUNK
    #undef STS_CHUNK
}

// ---------------------------------------------------------------------------
// RoPE (in-place). x layout: [S, nheads*128]. cos/sin: [S, 128].
// ---------------------------------------------------------------------------
__global__ void rope_kernel(float* __restrict__ x,
                            const float* __restrict__ cosp,
                            const float* __restrict__ sinp,
                            int nheads)
{
    int idx = blockIdx.x * blockDim.x + threadIdx.x;
    int total = S_LEN * nheads * 64;
    if (idx >= total) return;
    int d = idx & 63;
    int t = idx >> 6;
    int hh = t % nheads;
    int s = t / nheads;
    size_t b = (size_t)s * nheads * HD + hh * HD;
    float x1 = x[b + d];
    float x2 = x[b + d + 64];
    float c1 = cosp[s * HD + d],      s1 = sinp[s * HD + d];
    float c2 = cosp[s * HD + d + 64], s2 = sinp[s * HD + d + 64];
    x[b + d]      = x1 * c1 - x2 * s1;
    x[b + d + 64] = x2 * c2 + x1 * s2;
}

// ---------------------------------------------------------------------------
// Flash attention fp32, causal, GQA (unchanged, known-good).
// ---------------------------------------------------------------------------
__global__ __launch_bounds__(256) void flash_attn(
    const float* __restrict__ Q, const float* __restrict__ Kp,
    const float* __restrict__ Vp, float* __restrict__ O)
{
    extern __shared__ float smf[];
    float* Qs = smf;
    float* Ks = Qs + 64 * 132;
    float* Vs = Ks + 64 * 132;
    float* Ps = Vs + 64 * 132;

    const int qb = gridDim.x - 1 - blockIdx.x;
    const int h = blockIdx.y;
    const int kvh = h / NREP;
    const int tid = threadIdx.x;
    const int tx = tid & 15, ty = tid >> 4;
    const int q0 = qb * 64;
    const float scale = 0.08838834764831845f;

    for (int i = tid; i < 64 * 32; i += 256) {
        int r = i >> 5, c4 = (i & 31) * 4;
        *(float4*)(Qs + r * 132 + c4) =
            *(const float4*)(Q + (size_t)(q0 + r) * QDIM + h * HD + c4);
    }

    float m_i[4], l_i[4];
    float o[4][8];
    #pragma unroll
    for (int i = 0; i < 4; i++) {
        m_i[i] = -INFINITY; l_i[i] = 0.f;
        #pragma unroll
        for (int j = 0; j < 8; j++) o[i][j] = 0.f;
    }

    for (int kb = 0; kb <= qb; kb++) {
        const int k0 = kb * 64;
        __syncthreads();
        for (int i = tid; i < 64 * 32; i += 256) {
            int r = i >> 5, c4 = (i & 31) * 4;
            size_t goff = (size_t)(k0 + r) * KVDIM + kvh * HD + c4;
            *(float4*)(Ks + r * 132 + c4) = *(const float4*)(Kp + goff);
            *(float4*)(Vs + r * 132 + c4) = *(const float4*)(Vp + goff);
        }
        __syncthreads();

        float s[4][4];
        #pragma unroll
        for (int i = 0; i < 4; i++)
            #pragma unroll
            for (int j = 0; j < 4; j++) s[i][j] = 0.f;

        for (int d = 0; d < 128; d += 4) {
            float4 qv[4], kv[4];
            #pragma unroll
            for (int i = 0; i < 4; i++)
                qv[i] = *(const float4*)(Qs + (ty + 16 * i) * 132 + d);
            #pragma unroll
            for (int j = 0; j < 4; j++)
                kv[j] = *(const float4*)(Ks + (tx + 16 * j) * 132 + d);
            #pragma unroll
            for (int i = 0; i < 4; i++)
                #pragma unroll
                for (int j = 0; j < 4; j++) {
                    s[i][j] = fmaf(qv[i].x, kv[j].x, s[i][j]);
                    s[i][j] = fmaf(qv[i].y, kv[j].y, s[i][j]);
                    s[i][j] = fmaf(qv[i].z, kv[j].z, s[i][j]);
                    s[i][j] = fmaf(qv[i].w, kv[j].w, s[i][j]);
                }
        }

        #pragma unroll
        for (int i = 0; i < 4; i++) {
            int rg = q0 + ty + 16 * i;
            #pragma unroll
            for (int j = 0; j < 4; j++) {
                int cg = k0 + tx + 16 * j;
                s[i][j] = (cg > rg) ? -INFINITY : s[i][j] * scale;
            }
        }

        #pragma unroll
        for (int i = 0; i < 4; i++) {
            float tmax = fmaxf(fmaxf(s[i][0], s[i][1]), fmaxf(s[i][2], s[i][3]));
            #pragma unroll
            for (int off = 1; off < 16; off <<= 1)
                tmax = fmaxf(tmax, __shfl_xor_sync(0xffffffffu, tmax, off));
            float m_new = fmaxf(m_i[i], tmax);
            float p0 = __expf(s[i][0] - m_new);
            float p1 = __expf(s[i][1] - m_new);
            float p2 = __expf(s[i][2] - m_new);
            float p3 = __expf(s[i][3] - m_new);
            float tsum = p0 + p1 + p2 + p3;
            #pragma unroll
            for (int off = 1; off < 16; off <<= 1)
                tsum += __shfl_xor_sync(0xffffffffu, tsum, off);
            float alpha = __expf(m_i[i] - m_new);
            l_i[i] = l_i[i] * alpha + tsum;
            m_i[i] = m_new;
            #pragma unroll
            for (int j = 0; j < 8; j++) o[i][j] *= alpha;
            int r = ty + 16 * i;
            Ps[r * 68 + tx + 0]  = p0;
            Ps[r * 68 + tx + 16] = p1;
            Ps[r * 68 + tx + 32] = p2;
            Ps[r * 68 + tx + 48] = p3;
        }
        __syncthreads();

        for (int jj = 0; jj < 64; jj++) {
            float4 va = *(const float4*)(Vs + jj * 132 + tx * 4);
            float4 vb = *(const float4*)(Vs + jj * 132 + 64 + tx * 4);
            #pragma unroll
            for (int i = 0; i < 4; i++) {
                float p = Ps[(ty + 16 * i) * 68 + jj];
                o[i][0] = fmaf(p, va.x, o[i][0]);
                o[i][1] = fmaf(p, va.y, o[i][1]);
                o[i][2] = fmaf(p, va.z, o[i][2]);
                o[i][3] = fmaf(p, va.w, o[i][3]);
                o[i][4] = fmaf(p, vb.x, o[i][4]);
                o[i][5] = fmaf(p, vb.y, o[i][5]);
                o[i][6] = fmaf(p, vb.z, o[i][6]);
                o[i][7] = fmaf(p, vb.w, o[i][7]);
            }
        }
    }

    #pragma unroll
    for (int i = 0; i < 4; i++) {
        float inv = 1.f / l_i[i];
        int r = q0 + ty + 16 * i;
        float4 ra, rb;
        ra.x = o[i][0] * inv; ra.y = o[i][1] * inv;
        ra.z = o[i][2] * inv; ra.w = o[i][3] * inv;
        rb.x = o[i][4] * inv; rb.y = o[i][5] * inv;
        rb.z = o[i][6] * inv; rb.w = o[i][7] * inv;
        *(float4*)(O + (size_t)r * QDIM + h * HD + tx * 4) = ra;
        *(float4*)(O + (size_t)r * QDIM + h * HD + 64 + tx * 4) = rb;
    }
}

// ---------------------------------------------------------------------------
extern "C" void kernel_launch(void* const* d_in, const int* in_sizes, int n_in,
                              void* d_out, int out_size)
{
    const float* X    = (const float*)d_in[0];
    const float* cosp = (const float*)d_in[1];
    const float* sinp = (const float*)d_in[2];
    // d_in[3] = attention_mask (causal by construction; applied analytically)
    const float* Wq = (const float*)d_in[4];
    const float* bq = (const float*)d_in[5];
    const float* Wk = (const float*)d_in[6];
    const float* bk = (const float*)d_in[7];
    const float* Wv = (const float*)d_in[8];
    const float* bv = (const float*)d_in[9];
    const float* Wo = (const float*)d_in[10];
    float* out = (float*)d_out;

    float *q, *k, *v, *att;
    cudaGetSymbolAddress((void**)&q, g_q);
    cudaGetSymbolAddress((void**)&k, g_k);
    cudaGetSymbolAddress((void**)&v, g_v);
    cudaGetSymbolAddress((void**)&att, g_att);

    cudaFuncSetAttribute(tcgemm_tf32, cudaFuncAttributeMaxDynamicSharedMemorySize, GEMM_SMEM);

    // QKV projections (tf32 mma.sync)
    tcgemm_tf32<<<dim3(QDIM / 128, S_LEN / 128), 256, GEMM_SMEM>>>(X, Wq, bq, q, S_LEN, QDIM, HIDDEN);
    tcgemm_tf32<<<dim3(KVDIM / 128, S_LEN / 128), 256, GEMM_SMEM>>>(X, Wk, bk, k, S_LEN, KVDIM, HIDDEN);
    tcgemm_tf32<<<dim3(KVDIM / 128, S_LEN / 128), 256, GEMM_SMEM>>>(X, Wv, bv, v, S_LEN, KVDIM, HIDDEN);

    // RoPE on q and k
    rope_kernel<<<(S_LEN * NH * 64 + 255) / 256, 256>>>(q, cosp, sinp, NH);
    rope_kernel<<<(S_LEN * NKV * 64 + 255) / 256, 256>>>(k, cosp, sinp, NKV);

    // Flash attention (fp32)
    size_t fa_smem = (size_t)(3 * 64 * 132 + 64 * 68) * sizeof(float);
    cudaFuncSetAttribute(flash_attn, cudaFuncAttributeMaxDynamicSharedMemorySize, (int)fa_smem);
    flash_attn<<<dim3(S_LEN / 64, NH), 256, fa_smem>>>(q, k, v, att);

    // Output projection (tf32 mma.sync) -> d_out
    tcgemm_tf32<<<dim3(QDIM / 128, S_LEN / 128), 256, GEMM_SMEM>>>(att, Wo, nullptr, out, S_LEN, QDIM, HIDDEN);
}

// round 4
// speedup vs baseline: 3.1970x; 1.6969x over previous
#include <cuda_runtime.h>
#include <math.h>
#include <stdint.h>

#define S_LEN 2048
#define HIDDEN 2048
#define NH 16
#define NKV 2
#define HD 128
#define QDIM (NH*HD)    // 2048
#define KVDIM (NKV*HD)  // 256
#define NREP (NH/NKV)   // 8

// Scratch (device globals; no allocation allowed)
__device__ float g_q[S_LEN * QDIM];
__device__ float g_k[S_LEN * KVDIM];
__device__ float g_v[S_LEN * KVDIM];
__device__ float g_att[S_LEN * QDIM];

// ===========================================================================
// helpers
// ===========================================================================
__device__ __forceinline__ uint32_t smem_to_u32(const void* p) {
    uint32_t a;
    asm("{ .reg .u64 t; cvta.to.shared.u64 t, %1; cvt.u32.u64 %0, t; }" : "=r"(a) : "l"(p));
    return a;
}
__device__ __forceinline__ uint32_t f2tf32(float f) {
    uint32_t r;
    asm("cvt.rna.tf32.f32 %0, %1;" : "=r"(r) : "f"(f));
    return r;
}
__device__ __forceinline__ void sts128u(uint32_t a, uint32_t x, uint32_t y, uint32_t z, uint32_t w) {
    asm volatile("st.shared.v4.b32 [%0], {%1,%2,%3,%4};" :: "r"(a), "r"(x), "r"(y), "r"(z), "r"(w) : "memory");
}
__device__ __forceinline__ void sts64u(uint32_t a, uint32_t x, uint32_t y) {
    asm volatile("st.shared.v2.b32 [%0], {%1,%2};" :: "r"(a), "r"(x), "r"(y) : "memory");
}
__device__ __forceinline__ uint32_t ldsu(uint32_t a) {
    uint32_t v; asm volatile("ld.shared.b32 %0, [%1];" : "=r"(v) : "r"(a)); return v;
}
__device__ __forceinline__ void mma_tf32(float* d, const uint32_t* a, const uint32_t* b) {
    asm volatile("mma.sync.aligned.m16n8k8.row.col.f32.tf32.tf32.f32 "
                 "{%0,%1,%2,%3}, {%4,%5,%6,%7}, {%8,%9}, {%0,%1,%2,%3};"
                 : "+f"(d[0]), "+f"(d[1]), "+f"(d[2]), "+f"(d[3])
                 : "r"(a[0]), "r"(a[1]), "r"(a[2]), "r"(a[3]), "r"(b[0]), "r"(b[1]));
}

// ===========================================================================
// tf32 mma.sync GEMM (unchanged from R3): C[M,N] = A[M,K] @ W[K,N] (+bias).
// ===========================================================================
#define AS_STRIDE 36
#define BS_STRIDE 136
#define AS_BYTES (128 * AS_STRIDE * 4)
#define BS_BYTES (32 * BS_STRIDE * 4)
#define GEMM_SMEM (2 * (AS_BYTES + BS_BYTES))

__global__ __launch_bounds__(256) void tcgemm_tf32(
    const float* __restrict__ A, const float* __restrict__ W,
    const float* __restrict__ bias, float* __restrict__ C,
    int M, int N, int K)
{
    extern __shared__ float sm[];
    const uint32_t smb = smem_to_u32(sm);
    const uint32_t ASb[2] = { smb, smb + AS_BYTES };
    const uint32_t BSb[2] = { smb + 2 * AS_BYTES, smb + 2 * AS_BYTES + BS_BYTES };

    const int tid = threadIdx.x;
    const int lane = tid & 31, wid = tid >> 5;
    const int wm = wid & 1, wn = wid >> 1;
    const int r1 = lane >> 2, cc = lane & 3;
    const int row0 = blockIdx.y * 128, col0 = blockIdx.x * 128;
    const int NC = K >> 5;

    const int am = tid >> 3;
    const int kq = tid & 7;
    const int bk = tid >> 5;
    const int nq = tid & 31;

    float acc[4][4][4];
    #pragma unroll
    for (int mt = 0; mt < 4; mt++)
        #pragma unroll
        for (int nt = 0; nt < 4; nt++)
            #pragma unroll
            for (int i = 0; i < 4; i++) acc[mt][nt][i] = 0.f;

    float4 pa[4], pb[4];

    #define LDG_CHUNK(c) do { \
        _Pragma("unroll") \
        for (int t = 0; t < 4; t++) \
            pa[t] = *(const float4*)(A + (size_t)(row0 + am + 32 * t) * K + (c) * 32 + kq * 4); \
        _Pragma("unroll") \
        for (int t = 0; t < 4; t++) \
            pb[t] = *(const float4*)(W + (size_t)((c) * 32 + bk + 8 * t) * N + col0 + nq * 4); \
    } while (0)

    #define STS_CHUNK(buf) do { \
        _Pragma("unroll") \
        for (int t = 0; t < 4; t++) { \
            uint32_t ad = ASb[buf] + (uint32_t)(((am + 32 * t) * AS_STRIDE + kq * 4) * 4); \
            sts128u(ad, f2tf32(pa[t].x), f2tf32(pa[t].y), f2tf32(pa[t].z), f2tf32(pa[t].w)); \
        } \
        _Pragma("unroll") \
        for (int t = 0; t < 4; t++) { \
            uint32_t bd = BSb[buf] + (uint32_t)(((bk + 8 * t) * BS_STRIDE + nq * 4) * 4); \
            sts128u(bd, f2tf32(pb[t].x), f2tf32(pb[t].y), f2tf32(pb[t].z), f2tf32(pb[t].w)); \
        } \
    } while (0)

    LDG_CHUNK(0);
    STS_CHUNK(0);
    __syncthreads();

    for (int c = 0; c < NC; c++) {
        const int cur = c & 1;
        if (c + 1 < NC) LDG_CHUNK(c + 1);

        const uint32_t AS = ASb[cur], BS = BSb[cur];
        #pragma unroll
        for (int ks = 0; ks < 4; ks++) {
            uint32_t afr[4][4], bfr[4][2];
            #pragma unroll
            for (int mt = 0; mt < 4; mt++) {
                uint32_t base = AS + (uint32_t)((((wm * 64 + mt * 16 + r1) * AS_STRIDE) + ks * 8 + cc) * 4);
                afr[mt][0] = ldsu(base);
                afr[mt][1] = ldsu(base + 8 * AS_STRIDE * 4);
                afr[mt][2] = ldsu(base + 16);
                afr[mt][3] = ldsu(base + 8 * AS_STRIDE * 4 + 16);
            }
            #pragma unroll
            for (int nt = 0; nt < 4; nt++) {
                uint32_t nb = BS + (uint32_t)((((ks * 8 + cc) * BS_STRIDE) + wn * 32 + nt * 8 + r1) * 4);
                bfr[nt][0] = ldsu(nb);
                bfr[nt][1] = ldsu(nb + 4 * BS_STRIDE * 4);
            }
            #pragma unroll
            for (int mt = 0; mt < 4; mt++)
                #pragma unroll
                for (int nt = 0; nt < 4; nt++)
                    mma_tf32(acc[mt][nt], afr[mt], bfr[nt]);
        }

        if (c + 1 < NC) STS_CHUNK((c + 1) & 1);
        __syncthreads();
    }

    #pragma unroll
    for (int mt = 0; mt < 4; mt++) {
        int r = row0 + wm * 64 + mt * 16 + r1;
        #pragma unroll
        for (int nt = 0; nt < 4; nt++) {
            int col = col0 + wn * 32 + nt * 8 + 2 * cc;
            float bx = 0.f, by = 0.f;
            if (bias) { bx = bias[col]; by = bias[col + 1]; }
            float2 v0, v1;
            v0.x = acc[mt][nt][0] + bx; v0.y = acc[mt][nt][1] + by;
            v1.x = acc[mt][nt][2] + bx; v1.y = acc[mt][nt][3] + by;
            *(float2*)(C + (size_t)r * N + col) = v0;
            *(float2*)(C + (size_t)(r + 8) * N + col) = v1;
        }
    }
    #undef LDG_CHUNK
    #undef STS_CHUNK
}

// ---------------------------------------------------------------------------
// RoPE (in-place). x layout: [S, nheads*128]. cos/sin: [S, 128].
// ---------------------------------------------------------------------------
__global__ void rope_kernel(float* __restrict__ x,
                            const float* __restrict__ cosp,
                            const float* __restrict__ sinp,
                            int nheads)
{
    int idx = blockIdx.x * blockDim.x + threadIdx.x;
    int total = S_LEN * nheads * 64;
    if (idx >= total) return;
    int d = idx & 63;
    int t = idx >> 6;
    int hh = t % nheads;
    int s = t / nheads;
    size_t b = (size_t)s * nheads * HD + hh * HD;
    float x1 = x[b + d];
    float x2 = x[b + d + 64];
    float c1 = cosp[s * HD + d],      s1 = sinp[s * HD + d];
    float c2 = cosp[s * HD + d + 64], s2 = sinp[s * HD + d + 64];
    x[b + d]      = x1 * c1 - x2 * s1;
    x[b + d + 64] = x2 * c2 + x1 * s2;
}

// ===========================================================================
// Flash attention, tf32 mma.sync. CTA = 64 q-rows x 1 head, 128 threads,
// 4 warps; warp w owns rows w*16..w*16+15 (full row per warp -> quad-local
// softmax reduction). Q as register A-fragments; K/V smem stride 132
// (conflict-free for both QK^T and PV B-frag reads); P via smem stride 68.
// ===========================================================================
#define KS_STRIDE 132
#define PS_STRIDE 68
#define FA_SMEM ((2 * 64 * KS_STRIDE + 64 * PS_STRIDE) * 4)   // 84992 B

__global__ __launch_bounds__(128) void flash_attn_tc(
    const float* __restrict__ Q, const float* __restrict__ Kp,
    const float* __restrict__ Vp, float* __restrict__ O)
{
    extern __shared__ float smf[];
    const uint32_t Ksb = smem_to_u32(smf);
    const uint32_t Vsb = Ksb + 64 * KS_STRIDE * 4;
    const uint32_t Psb = Vsb + 64 * KS_STRIDE * 4;

    const int qb = gridDim.x - 1 - blockIdx.x;   // heavy blocks first
    const int h = blockIdx.y;
    const int kvh = h / NREP;
    const int tid = threadIdx.x;
    const int lane = tid & 31, wid = tid >> 5;
    const int r4 = lane >> 2, cc = lane & 3;
    const int q0 = qb * 64;
    const int m0 = wid * 16;
    const float scale = 0.08838834764831845f;    // 1/sqrt(128)

    // Q fragments in registers (loaded once, rna-rounded to tf32)
    uint32_t qfrag[16][4];
    {
        const float* qA = Q + (size_t)(q0 + m0 + r4) * QDIM + h * HD;
        const float* qB = qA + 8 * QDIM;
        #pragma unroll
        for (int kt = 0; kt < 16; kt++) {
            qfrag[kt][0] = f2tf32(qA[kt * 8 + cc]);
            qfrag[kt][1] = f2tf32(qB[kt * 8 + cc]);
            qfrag[kt][2] = f2tf32(qA[kt * 8 + cc + 4]);
            qfrag[kt][3] = f2tf32(qB[kt * 8 + cc + 4]);
        }
    }

    float mA = -1e30f, mB = -1e30f, lA = 0.f, lB = 0.f;
    float ofrag[16][4];
    #pragma unroll
    for (int nt = 0; nt < 16; nt++)
        #pragma unroll
        for (int j = 0; j < 4; j++) ofrag[nt][j] = 0.f;

    const int rgA = q0 + m0 + r4;       // global row (low)
    const int rgB = rgA + 8;            // global row (high)

    for (int kb = 0; kb <= qb; kb++) {
        const int k0 = kb * 64;
        __syncthreads();
        // load K,V tiles (64 x 128 each), cvt to tf32, stride-132 smem
        #pragma unroll
        for (int t = 0; t < 16; t++) {
            int i = tid + t * 128;
            int r = i >> 5, c4 = (i & 31) * 4;
            size_t goff = (size_t)(k0 + r) * KVDIM + kvh * HD + c4;
            float4 kv = *(const float4*)(Kp + goff);
            float4 vv = *(const float4*)(Vp + goff);
            uint32_t soff = (uint32_t)((r * KS_STRIDE + c4) * 4);
            sts128u(Ksb + soff, f2tf32(kv.x), f2tf32(kv.y), f2tf32(kv.z), f2tf32(kv.w));
            sts128u(Vsb + soff, f2tf32(vv.x), f2tf32(vv.y), f2tf32(vv.z), f2tf32(vv.w));
        }
        __syncthreads();

        // ---- S = Q K^T (16 x 64 per warp) ----
        float sfr[8][4];
        #pragma unroll
        for (int nt = 0; nt < 8; nt++)
            #pragma unroll
            for (int j = 0; j < 4; j++) sfr[nt][j] = 0.f;

        #pragma unroll
        for (int kt = 0; kt < 16; kt++) {
            uint32_t bfr[8][2];
            #pragma unroll
            for (int nt = 0; nt < 8; nt++) {
                uint32_t ba = Ksb + (uint32_t)((((nt * 8 + r4) * KS_STRIDE) + kt * 8 + cc) * 4);
                bfr[nt][0] = ldsu(ba);
                bfr[nt][1] = ldsu(ba + 16);
            }
            #pragma unroll
            for (int nt = 0; nt < 8; nt++)
                mma_tf32(sfr[nt], qfrag[kt], bfr[nt]);
        }

        // ---- scale + causal mask ----
        const bool diag = (kb == qb);
        #pragma unroll
        for (int nt = 0; nt < 8; nt++) {
            int cg = k0 + nt * 8 + 2 * cc;
            sfr[nt][0] *= scale; sfr[nt][1] *= scale;
            sfr[nt][2] *= scale; sfr[nt][3] *= scale;
            if (diag) {
                if (cg     > rgA) sfr[nt][0] = -1e30f;
                if (cg + 1 > rgA) sfr[nt][1] = -1e30f;
                if (cg     > rgB) sfr[nt][2] = -1e30f;
                if (cg + 1 > rgB) sfr[nt][3] = -1e30f;
            }
        }

        // ---- online softmax (rows rgA, rgB; quad-local reduce) ----
        float rmA = -1e30f, rmB = -1e30f;
        #pragma unroll
        for (int nt = 0; nt < 8; nt++) {
            rmA = fmaxf(rmA, fmaxf(sfr[nt][0], sfr[nt][1]));
            rmB = fmaxf(rmB, fmaxf(sfr[nt][2], sfr[nt][3]));
        }
        rmA = fmaxf(rmA, __shfl_xor_sync(0xffffffffu, rmA, 1));
        rmA = fmaxf(rmA, __shfl_xor_sync(0xffffffffu, rmA, 2));
        rmB = fmaxf(rmB, __shfl_xor_sync(0xffffffffu, rmB, 1));
        rmB = fmaxf(rmB, __shfl_xor_sync(0xffffffffu, rmB, 2));

        float mnA = fmaxf(mA, rmA), mnB = fmaxf(mB, rmB);
        float aA = __expf(mA - mnA), aB = __expf(mB - mnB);
        mA = mnA; mB = mnB;

        float smA = 0.f, smB = 0.f;
        #pragma unroll
        for (int nt = 0; nt < 8; nt++) {
            sfr[nt][0] = __expf(sfr[nt][0] - mnA);
            sfr[nt][1] = __expf(sfr[nt][1] - mnA);
            sfr[nt][2] = __expf(sfr[nt][2] - mnB);
            sfr[nt][3] = __expf(sfr[nt][3] - mnB);
            smA += sfr[nt][0] + sfr[nt][1];
            smB += sfr[nt][2] + sfr[nt][3];
        }
        smA += __shfl_xor_sync(0xffffffffu, smA, 1);
        smA += __shfl_xor_sync(0xffffffffu, smA, 2);
        smB += __shfl_xor_sync(0xffffffffu, smB, 1);
        smB += __shfl_xor_sync(0xffffffffu, smB, 2);
        lA = lA * aA + smA;
        lB = lB * aB + smB;

        #pragma unroll
        for (int nt = 0; nt < 16; nt++) {
            ofrag[nt][0] *= aA; ofrag[nt][1] *= aA;
            ofrag[nt][2] *= aB; ofrag[nt][3] *= aB;
        }

        // ---- P to smem (own rows only) ----
        #pragma unroll
        for (int nt = 0; nt < 8; nt++) {
            uint32_t pa0 = Psb + (uint32_t)((((m0 + r4) * PS_STRIDE) + nt * 8 + 2 * cc) * 4);
            sts64u(pa0, f2tf32(sfr[nt][0]), f2tf32(sfr[nt][1]));
            sts64u(pa0 + 8 * PS_STRIDE * 4, f2tf32(sfr[nt][2]), f2tf32(sfr[nt][3]));
        }
        __syncwarp();

        // ---- O += P @ V ----
        #pragma unroll
        for (int kt = 0; kt < 8; kt++) {
            uint32_t afr[4];
            uint32_t pb = Psb + (uint32_t)((((m0 + r4) * PS_STRIDE) + kt * 8 + cc) * 4);
            afr[0] = ldsu(pb);
            afr[1] = ldsu(pb + 8 * PS_STRIDE * 4);
            afr[2] = ldsu(pb + 16);
            afr[3] = ldsu(pb + 8 * PS_STRIDE * 4 + 16);
            #pragma unroll
            for (int nt = 0; nt < 16; nt++) {
                uint32_t vb = Vsb + (uint32_t)((((kt * 8 + cc) * KS_STRIDE) + nt * 8 + r4) * 4);
                uint32_t b0 = ldsu(vb);
                uint32_t b1 = ldsu(vb + 4 * KS_STRIDE * 4);
                uint32_t bfr[2] = { b0, b1 };
                mma_tf32(ofrag[nt], afr, bfr);
            }
        }
    }

    // ---- epilogue ----
    const float iA = 1.f / lA, iB = 1.f / lB;
    #pragma unroll
    for (int nt = 0; nt < 16; nt++) {
        int col = h * HD + nt * 8 + 2 * cc;
        float2 vA, vB;
        vA.x = ofrag[nt][0] * iA; vA.y = ofrag[nt][1] * iA;
        vB.x = ofrag[nt][2] * iB; vB.y = ofrag[nt][3] * iB;
        *(float2*)(O + (size_t)rgA * QDIM + col) = vA;
        *(float2*)(O + (size_t)rgB * QDIM + col) = vB;
    }
}

// ---------------------------------------------------------------------------
extern "C" void kernel_launch(void* const* d_in, const int* in_sizes, int n_in,
                              void* d_out, int out_size)
{
    const float* X    = (const float*)d_in[0];
    const float* cosp = (const float*)d_in[1];
    const float* sinp = (const float*)d_in[2];
    // d_in[3] = attention_mask (causal by construction; applied analytically)
    const float* Wq = (const float*)d_in[4];
    const float* bq = (const float*)d_in[5];
    const float* Wk = (const float*)d_in[6];
    const float* bk = (const float*)d_in[7];
    const float* Wv = (const float*)d_in[8];
    const float* bv = (const float*)d_in[9];
    const float* Wo = (const float*)d_in[10];
    float* out = (float*)d_out;

    float *q, *k, *v, *att;
    cudaGetSymbolAddress((void**)&q, g_q);
    cudaGetSymbolAddress((void**)&k, g_k);
    cudaGetSymbolAddress((void**)&v, g_v);
    cudaGetSymbolAddress((void**)&att, g_att);

    cudaFuncSetAttribute(tcgemm_tf32, cudaFuncAttributeMaxDynamicSharedMemorySize, GEMM_SMEM);
    cudaFuncSetAttribute(flash_attn_tc, cudaFuncAttributeMaxDynamicSharedMemorySize, FA_SMEM);

    // QKV projections (tf32 mma.sync)
    tcgemm_tf32<<<dim3(QDIM / 128, S_LEN / 128), 256, GEMM_SMEM>>>(X, Wq, bq, q, S_LEN, QDIM, HIDDEN);
    tcgemm_tf32<<<dim3(KVDIM / 128, S_LEN / 128), 256, GEMM_SMEM>>>(X, Wk, bk, k, S_LEN, KVDIM, HIDDEN);
    tcgemm_tf32<<<dim3(KVDIM / 128, S_LEN / 128), 256, GEMM_SMEM>>>(X, Wv, bv, v, S_LEN, KVDIM, HIDDEN);

    // RoPE on q and k
    rope_kernel<<<(S_LEN * NH * 64 + 255) / 256, 256>>>(q, cosp, sinp, NH);
    rope_kernel<<<(S_LEN * NKV * 64 + 255) / 256, 256>>>(k, cosp, sinp, NKV);

    // Flash attention (tf32 mma.sync)
    flash_attn_tc<<<dim3(S_LEN / 64, NH), 128, FA_SMEM>>>(q, k, v, att);

    // Output projection (tf32 mma.sync) -> d_out
    tcgemm_tf32<<<dim3(QDIM / 128, S_LEN / 128), 256, GEMM_SMEM>>>(att, Wo, nullptr, out, S_LEN, QDIM, HIDDEN);
}

// round 8
// speedup vs baseline: 3.8083x; 1.1912x over previous
#include <cuda_runtime.h>
#include <math.h>
#include <stdint.h>

#define S_LEN 2048
#define HIDDEN 2048
#define NH 16
#define NKV 2
#define HD 128
#define QDIM (NH*HD)    // 2048
#define KVDIM (NKV*HD)  // 256
#define NREP (NH/NKV)   // 8

// Scratch (device globals; no allocation allowed)
__device__ float g_q[S_LEN * QDIM];
__device__ float g_k[S_LEN * KVDIM];
__device__ float g_v[S_LEN * KVDIM];
__device__ float g_att[S_LEN * QDIM];
__device__ float g_part[2 * S_LEN * 512];   // split-K partials for fused KV

// ===========================================================================
// helpers
// ===========================================================================
__device__ __forceinline__ uint32_t smem_to_u32(const void* p) {
    uint32_t a;
    asm("{ .reg .u64 t; cvta.to.shared.u64 t, %1; cvt.u32.u64 %0, t; }" : "=r"(a) : "l"(p));
    return a;
}
__device__ __forceinline__ uint32_t f2tf32(float f) {
    uint32_t r;
    asm("cvt.rna.tf32.f32 %0, %1;" : "=r"(r) : "f"(f));
    return r;
}
__device__ __forceinline__ void sts128u(uint32_t a, uint32_t x, uint32_t y, uint32_t z, uint32_t w) {
    asm volatile("st.shared.v4.b32 [%0], {%1,%2,%3,%4};" :: "r"(a), "r"(x), "r"(y), "r"(z), "r"(w) : "memory");
}
__device__ __forceinline__ void sts64u(uint32_t a, uint32_t x, uint32_t y) {
    asm volatile("st.shared.v2.b32 [%0], {%1,%2};" :: "r"(a), "r"(x), "r"(y) : "memory");
}
__device__ __forceinline__ uint32_t ldsu(uint32_t a) {
    uint32_t v; asm volatile("ld.shared.b32 %0, [%1];" : "=r"(v) : "r"(a)); return v;
}
__device__ __forceinline__ void mma_tf32(float* d, const uint32_t* a, const uint32_t* b) {
    asm volatile("mma.sync.aligned.m16n8k8.row.col.f32.tf32.tf32.f32 "
                 "{%0,%1,%2,%3}, {%4,%5,%6,%7}, {%8,%9}, {%0,%1,%2,%3};"
                 : "+f"(d[0]), "+f"(d[1]), "+f"(d[2]), "+f"(d[3])
                 : "r"(a[0]), "r"(a[1]), "r"(a[2]), "r"(a[3]), "r"(b[0]), "r"(b[1]));
}

// ===========================================================================
// tf32 mma.sync GEMM: C[M,N] = A[M,K] @ W[K,N] (+bias). 128x128 tile, BK=32.
// ===========================================================================
#define AS_STRIDE 36
#define BS_STRIDE 136
#define AS_BYTES (128 * AS_STRIDE * 4)
#define BS_BYTES (32 * BS_STRIDE * 4)
#define GEMM_SMEM (2 * (AS_BYTES + BS_BYTES))

#define LDG_CHUNK(c, A, W, Kstr, Nstr, bcol0) do { \
    _Pragma("unroll") \
    for (int t = 0; t < 4; t++) \
        pa[t] = *(const float4*)((A) + (size_t)(row0 + am + 32 * t) * (Kstr) + (c) * 32 + kq * 4); \
    _Pragma("unroll") \
    for (int t = 0; t < 4; t++) \
        pb[t] = *(const float4*)((W) + (size_t)((c) * 32 + bk + 8 * t) * (Nstr) + (bcol0) + nq * 4); \
} while (0)

#define STS_CHUNK(buf) do { \
    _Pragma("unroll") \
    for (int t = 0; t < 4; t++) { \
        uint32_t ad = ASb[buf] + (uint32_t)(((am + 32 * t) * AS_STRIDE + kq * 4) * 4); \
        sts128u(ad, f2tf32(pa[t].x), f2tf32(pa[t].y), f2tf32(pa[t].z), f2tf32(pa[t].w)); \
    } \
    _Pragma("unroll") \
    for (int t = 0; t < 4; t++) { \
        uint32_t bd = BSb[buf] + (uint32_t)(((bk + 8 * t) * BS_STRIDE + nq * 4) * 4); \
        sts128u(bd, f2tf32(pb[t].x), f2tf32(pb[t].y), f2tf32(pb[t].z), f2tf32(pb[t].w)); \
    } \
} while (0)

#define GEMM_COMPUTE(cur) do { \
    const uint32_t AS = ASb[cur], BS = BSb[cur]; \
    _Pragma("unroll") \
    for (int ks = 0; ks < 4; ks++) { \
        uint32_t afr[4][4], bfr[4][2]; \
        _Pragma("unroll") \
        for (int mt = 0; mt < 4; mt++) { \
            uint32_t base = AS + (uint32_t)((((wm * 64 + mt * 16 + r1) * AS_STRIDE) + ks * 8 + cc) * 4); \
            afr[mt][0] = ldsu(base); \
            afr[mt][1] = ldsu(base + 8 * AS_STRIDE * 4); \
            afr[mt][2] = ldsu(base + 16); \
            afr[mt][3] = ldsu(base + 8 * AS_STRIDE * 4 + 16); \
        } \
        _Pragma("unroll") \
        for (int nt = 0; nt < 4; nt++) { \
            uint32_t nb = BS + (uint32_t)((((ks * 8 + cc) * BS_STRIDE) + wn * 32 + nt * 8 + r1) * 4); \
            bfr[nt][0] = ldsu(nb); \
            bfr[nt][1] = ldsu(nb + 4 * BS_STRIDE * 4); \
        } \
        _Pragma("unroll") \
        for (int mt = 0; mt < 4; mt++) \
            _Pragma("unroll") \
            for (int nt = 0; nt < 4; nt++) \
                mma_tf32(acc[mt][nt], afr[mt], bfr[nt]); \
    } \
} while (0)

__global__ __launch_bounds__(256) void tcgemm_tf32(
    const float* __restrict__ A, const float* __restrict__ W,
    const float* __restrict__ bias, float* __restrict__ C,
    int M, int N, int K)
{
    extern __shared__ float sm[];
    const uint32_t smb = smem_to_u32(sm);
    const uint32_t ASb[2] = { smb, smb + AS_BYTES };
    const uint32_t BSb[2] = { smb + 2 * AS_BYTES, smb + 2 * AS_BYTES + BS_BYTES };

    const int tid = threadIdx.x;
    const int lane = tid & 31, wid = tid >> 5;
    const int wm = wid & 1, wn = wid >> 1;
    const int r1 = lane >> 2, cc = lane & 3;
    const int row0 = blockIdx.y * 128, col0 = blockIdx.x * 128;
    const int NC = K >> 5;

    const int am = tid >> 3;
    const int kq = tid & 7;
    const int bk = tid >> 5;
    const int nq = tid & 31;

    float acc[4][4][4];
    #pragma unroll
    for (int mt = 0; mt < 4; mt++)
        #pragma unroll
        for (int nt = 0; nt < 4; nt++)
            #pragma unroll
            for (int i = 0; i < 4; i++) acc[mt][nt][i] = 0.f;

    float4 pa[4], pb[4];

    LDG_CHUNK(0, A, W, K, N, col0);
    STS_CHUNK(0);
    __syncthreads();

    for (int c = 0; c < NC; c++) {
        const int cur = c & 1;
        if (c + 1 < NC) LDG_CHUNK(c + 1, A, W, K, N, col0);
        GEMM_COMPUTE(cur);
        if (c + 1 < NC) STS_CHUNK((c + 1) & 1);
        __syncthreads();
    }

    #pragma unroll
    for (int mt = 0; mt < 4; mt++) {
        int r = row0 + wm * 64 + mt * 16 + r1;
        #pragma unroll
        for (int nt = 0; nt < 4; nt++) {
            int col = col0 + wn * 32 + nt * 8 + 2 * cc;
            float bx = 0.f, by = 0.f;
            if (bias) { bx = bias[col]; by = bias[col + 1]; }
            float2 v0, v1;
            v0.x = acc[mt][nt][0] + bx; v0.y = acc[mt][nt][1] + by;
            v1.x = acc[mt][nt][2] + bx; v1.y = acc[mt][nt][3] + by;
            *(float2*)(C + (size_t)r * N + col) = v0;
            *(float2*)(C + (size_t)(r + 8) * N + col) = v1;
        }
    }
}

// ===========================================================================
// Fused K+V projection with split-K=2.
// Grid (4, 16, 2). blockIdx.x: 0-1 -> K cols, 2-3 -> V cols (fused N=512).
// blockIdx.z: K-range [z*1024, +1024). Partials to g_part (no bias).
// ===========================================================================
__global__ __launch_bounds__(256) void kv_gemm_tf32(
    const float* __restrict__ A, const float* __restrict__ Wk,
    const float* __restrict__ Wv, float* __restrict__ Cpart)
{
    extern __shared__ float sm[];
    const uint32_t smb = smem_to_u32(sm);
    const uint32_t ASb[2] = { smb, smb + AS_BYTES };
    const uint32_t BSb[2] = { smb + 2 * AS_BYTES, smb + 2 * AS_BYTES + BS_BYTES };

    const int tid = threadIdx.x;
    const int lane = tid & 31, wid = tid >> 5;
    const int wm = wid & 1, wn = wid >> 1;
    const int r1 = lane >> 2, cc = lane & 3;
    const int row0 = blockIdx.y * 128;
    const int fcol0 = blockIdx.x * 128;                 // fused col in [0,512)
    const float* W = (blockIdx.x < 2) ? Wk : Wv;
    const int bcol0 = (blockIdx.x & 1) * 128;           // col within Wk/Wv
    const int cbase = blockIdx.z * 32;                  // chunk offset (K split)
    float* C = Cpart + (size_t)blockIdx.z * S_LEN * 512;

    const int am = tid >> 3;
    const int kq = tid & 7;
    const int bk = tid >> 5;
    const int nq = tid & 31;

    float acc[4][4][4];
    #pragma unroll
    for (int mt = 0; mt < 4; mt++)
        #pragma unroll
        for (int nt = 0; nt < 4; nt++)
            #pragma unroll
            for (int i = 0; i < 4; i++) acc[mt][nt][i] = 0.f;

    float4 pa[4], pb[4];

    LDG_CHUNK(cbase, A, W, HIDDEN, KVDIM, bcol0);
    STS_CHUNK(0);
    __syncthreads();

    for (int c = 0; c < 32; c++) {
        const int cur = c & 1;
        if (c + 1 < 32) LDG_CHUNK(cbase + c + 1, A, W, HIDDEN, KVDIM, bcol0);
        GEMM_COMPUTE(cur);
        if (c + 1 < 32) STS_CHUNK((c + 1) & 1);
        __syncthreads();
    }

    #pragma unroll
    for (int mt = 0; mt < 4; mt++) {
        int r = row0 + wm * 64 + mt * 16 + r1;
        #pragma unroll
        for (int nt = 0; nt < 4; nt++) {
            int col = fcol0 + wn * 32 + nt * 8 + 2 * cc;
            float2 v0, v1;
            v0.x = acc[mt][nt][0]; v0.y = acc[mt][nt][1];
            v1.x = acc[mt][nt][2]; v1.y = acc[mt][nt][3];
            *(float2*)(C + (size_t)r * 512 + col) = v0;
            *(float2*)(C + (size_t)(r + 8) * 512 + col) = v1;
        }
    }
}

// ===========================================================================
// KV finisher: reduce split-K partials + bias; RoPE for K; write g_k, g_v.
// Thread handles one (s, kvhead, d4) with d4 in [0,16): float4 at d and d+64.
// ===========================================================================
__global__ __launch_bounds__(256) void kv_finish(
    const float* __restrict__ part, const float* __restrict__ bkb,
    const float* __restrict__ bvb, const float* __restrict__ cosp,
    const float* __restrict__ sinp, float* __restrict__ Kout,
    float* __restrict__ Vout)
{
    int idx = blockIdx.x * blockDim.x + threadIdx.x;   // [0, 2048*2*16)
    int d4 = (idx & 15) * 4;
    int kh = (idx >> 4) & 1;
    int s  = idx >> 5;
    if (s >= S_LEN) return;

    const size_t rbase = (size_t)s * 512;
    const size_t pz = (size_t)S_LEN * 512;
    int kc = kh * HD;

    // K: cols kc+d4 (lo) and kc+64+d4 (hi)
    float4 klo = *(const float4*)(part + rbase + kc + d4);
    float4 khi = *(const float4*)(part + rbase + kc + 64 + d4);
    float4 klo2 = *(const float4*)(part + pz + rbase + kc + d4);
    float4 khi2 = *(const float4*)(part + pz + rbase + kc + 64 + d4);
    klo.x += klo2.x; klo.y += klo2.y; klo.z += klo2.z; klo.w += klo2.w;
    khi.x += khi2.x; khi.y += khi2.y; khi.z += khi2.z; khi.w += khi2.w;
    float4 bl = *(const float4*)(bkb + kc + d4);
    float4 bh = *(const float4*)(bkb + kc + 64 + d4);
    klo.x += bl.x; klo.y += bl.y; klo.z += bl.z; klo.w += bl.w;
    khi.x += bh.x; khi.y += bh.y; khi.z += bh.z; khi.w += bh.w;

    float4 c1 = *(const float4*)(cosp + s * HD + d4);
    float4 s1 = *(const float4*)(sinp + s * HD + d4);
    float4 c2 = *(const float4*)(cosp + s * HD + 64 + d4);
    float4 s2 = *(const float4*)(sinp + s * HD + 64 + d4);

    float4 rlo, rhi;
    rlo.x = klo.x * c1.x - khi.x * s1.x;
    rlo.y = klo.y * c1.y - khi.y * s1.y;
    rlo.z = klo.z * c1.z - khi.z * s1.z;
    rlo.w = klo.w * c1.w - khi.w * s1.w;
    rhi.x = khi.x * c2.x + klo.x * s2.x;
    rhi.y = khi.y * c2.y + klo.y * s2.y;
    rhi.z = khi.z * c2.z + klo.z * s2.z;
    rhi.w = khi.w * c2.w + klo.w * s2.w;

    *(float4*)(Kout + (size_t)s * KVDIM + kc + d4) = rlo;
    *(float4*)(Kout + (size_t)s * KVDIM + kc + 64 + d4) = rhi;

    // V: fused cols 256 + kc + d4 / +64
    float4 vlo = *(const float4*)(part + rbase + 256 + kc + d4);
    float4 vhi = *(const float4*)(part + rbase + 256 + kc + 64 + d4);
    float4 vlo2 = *(const float4*)(part + pz + rbase + 256 + kc + d4);
    float4 vhi2 = *(const float4*)(part + pz + rbase + 256 + kc + 64 + d4);
    float4 vbl = *(const float4*)(bvb + kc + d4);
    float4 vbh = *(const float4*)(bvb + kc + 64 + d4);
    vlo.x += vlo2.x + vbl.x; vlo.y += vlo2.y + vbl.y;
    vlo.z += vlo2.z + vbl.z; vlo.w += vlo2.w + vbl.w;
    vhi.x += vhi2.x + vbh.x; vhi.y += vhi2.y + vbh.y;
    vhi.z += vhi2.z + vbh.z; vhi.w += vhi2.w + vbh.w;

    *(float4*)(Vout + (size_t)s * KVDIM + kc + d4) = vlo;
    *(float4*)(Vout + (size_t)s * KVDIM + kc + 64 + d4) = vhi;
}

// ---------------------------------------------------------------------------
// RoPE for Q (in-place, vectorized float4). x: [S, 16*128]. cos/sin: [S,128].
// ---------------------------------------------------------------------------
__global__ __launch_bounds__(256) void rope_q(
    float* __restrict__ x, const float* __restrict__ cosp,
    const float* __restrict__ sinp)
{
    int idx = blockIdx.x * blockDim.x + threadIdx.x;   // [0, 2048*16*16)
    int d4 = (idx & 15) * 4;
    int hh = (idx >> 4) & 15;
    int s  = idx >> 8;
    if (s >= S_LEN) return;
    size_t b = (size_t)s * QDIM + hh * HD;

    float4 x1 = *(float4*)(x + b + d4);
    float4 x2 = *(float4*)(x + b + 64 + d4);
    float4 c1 = *(const float4*)(cosp + s * HD + d4);
    float4 s1 = *(const float4*)(sinp + s * HD + d4);
    float4 c2 = *(const float4*)(cosp + s * HD + 64 + d4);
    float4 s2 = *(const float4*)(sinp + s * HD + 64 + d4);

    float4 r1v, r2v;
    r1v.x = x1.x * c1.x - x2.x * s1.x;
    r1v.y = x1.y * c1.y - x2.y * s1.y;
    r1v.z = x1.z * c1.z - x2.z * s1.z;
    r1v.w = x1.w * c1.w - x2.w * s1.w;
    r2v.x = x2.x * c2.x + x1.x * s2.x;
    r2v.y = x2.y * c2.y + x1.y * s2.y;
    r2v.z = x2.z * c2.z + x1.z * s2.z;
    r2v.w = x2.w * c2.w + x1.w * s2.w;

    *(float4*)(x + b + d4) = r1v;
    *(float4*)(x + b + 64 + d4) = r2v;
}

// ===========================================================================
// Flash attention, tf32 mma.sync (unchanged from R4).
// ===========================================================================
#define KS_STRIDE 132
#define PS_STRIDE 68
#define FA_SMEM ((2 * 64 * KS_STRIDE + 64 * PS_STRIDE) * 4)

__global__ __launch_bounds__(128) void flash_attn_tc(
    const float* __restrict__ Q, const float* __restrict__ Kp,
    const float* __restrict__ Vp, float* __restrict__ O)
{
    extern __shared__ float smf[];
    const uint32_t Ksb = smem_to_u32(smf);
    const uint32_t Vsb = Ksb + 64 * KS_STRIDE * 4;
    const uint32_t Psb = Vsb + 64 * KS_STRIDE * 4;

    const int qb = gridDim.x - 1 - blockIdx.x;
    const int h = blockIdx.y;
    const int kvh = h / NREP;
    const int tid = threadIdx.x;
    const int lane = tid & 31, wid = tid >> 5;
    const int r4 = lane >> 2, cc = lane & 3;
    const int q0 = qb * 64;
    const int m0 = wid * 16;
    const float scale = 0.08838834764831845f;

    uint32_t qfrag[16][4];
    {
        const float* qA = Q + (size_t)(q0 + m0 + r4) * QDIM + h * HD;
        const float* qB = qA + 8 * QDIM;
        #pragma unroll
        for (int kt = 0; kt < 16; kt++) {
            qfrag[kt][0] = f2tf32(qA[kt * 8 + cc]);
            qfrag[kt][1] = f2tf32(qB[kt * 8 + cc]);
            qfrag[kt][2] = f2tf32(qA[kt * 8 + cc + 4]);
            qfrag[kt][3] = f2tf32(qB[kt * 8 + cc + 4]);
        }
    }

    float mA = -1e30f, mB = -1e30f, lA = 0.f, lB = 0.f;
    float ofrag[16][4];
    #pragma unroll
    for (int nt = 0; nt < 16; nt++)
        #pragma unroll
        for (int j = 0; j < 4; j++) ofrag[nt][j] = 0.f;

    const int rgA = q0 + m0 + r4;
    const int rgB = rgA + 8;

    for (int kb = 0; kb <= qb; kb++) {
        const int k0 = kb * 64;
        __syncthreads();
        #pragma unroll
        for (int t = 0; t < 16; t++) {
            int i = tid + t * 128;
            int r = i >> 5, c4 = (i & 31) * 4;
            size_t goff = (size_t)(k0 + r) * KVDIM + kvh * HD + c4;
            float4 kv = *(const float4*)(Kp + goff);
            float4 vv = *(const float4*)(Vp + goff);
            uint32_t soff = (uint32_t)((r * KS_STRIDE + c4) * 4);
            sts128u(Ksb + soff, f2tf32(kv.x), f2tf32(kv.y), f2tf32(kv.z), f2tf32(kv.w));
            sts128u(Vsb + soff, f2tf32(vv.x), f2tf32(vv.y), f2tf32(vv.z), f2tf32(vv.w));
        }
        __syncthreads();

        float sfr[8][4];
        #pragma unroll
        for (int nt = 0; nt < 8; nt++)
            #pragma unroll
            for (int j = 0; j < 4; j++) sfr[nt][j] = 0.f;

        #pragma unroll
        for (int kt = 0; kt < 16; kt++) {
            uint32_t bfr[8][2];
            #pragma unroll
            for (int nt = 0; nt < 8; nt++) {
                uint32_t ba = Ksb + (uint32_t)((((nt * 8 + r4) * KS_STRIDE) + kt * 8 + cc) * 4);
                bfr[nt][0] = ldsu(ba);
                bfr[nt][1] = ldsu(ba + 16);
            }
            #pragma unroll
            for (int nt = 0; nt < 8; nt++)
                mma_tf32(sfr[nt], qfrag[kt], bfr[nt]);
        }

        const bool diag = (kb == qb);
        #pragma unroll
        for (int nt = 0; nt < 8; nt++) {
            int cg = k0 + nt * 8 + 2 * cc;
            sfr[nt][0] *= scale; sfr[nt][1] *= scale;
            sfr[nt][2] *= scale; sfr[nt][3] *= scale;
            if (diag) {
                if (cg     > rgA) sfr[nt][0] = -1e30f;
                if (cg + 1 > rgA) sfr[nt][1] = -1e30f;
                if (cg     > rgB) sfr[nt][2] = -1e30f;
                if (cg + 1 > rgB) sfr[nt][3] = -1e30f;
            }
        }

        float rmA = -1e30f, rmB = -1e30f;
        #pragma unroll
        for (int nt = 0; nt < 8; nt++) {
            rmA = fmaxf(rmA, fmaxf(sfr[nt][0], sfr[nt][1]));
            rmB = fmaxf(rmB, fmaxf(sfr[nt][2], sfr[nt][3]));
        }
        rmA = fmaxf(rmA, __shfl_xor_sync(0xffffffffu, rmA, 1));
        rmA = fmaxf(rmA, __shfl_xor_sync(0xffffffffu, rmA, 2));
        rmB = fmaxf(rmB, __shfl_xor_sync(0xffffffffu, rmB, 1));
        rmB = fmaxf(rmB, __shfl_xor_sync(0xffffffffu, rmB, 2));

        float mnA = fmaxf(mA, rmA), mnB = fmaxf(mB, rmB);
        float aA = __expf(mA - mnA), aB = __expf(mB - mnB);
        mA = mnA; mB = mnB;

        float smA = 0.f, smB = 0.f;
        #pragma unroll
        for (int nt = 0; nt < 8; nt++) {
            sfr[nt][0] = __expf(sfr[nt][0] - mnA);
            sfr[nt][1] = __expf(sfr[nt][1] - mnA);
            sfr[nt][2] = __expf(sfr[nt][2] - mnB);
            sfr[nt][3] = __expf(sfr[nt][3] - mnB);
            smA += sfr[nt][0] + sfr[nt][1];
            smB += sfr[nt][2] + sfr[nt][3];
        }
        smA += __shfl_xor_sync(0xffffffffu, smA, 1);
        smA += __shfl_xor_sync(0xffffffffu, smA, 2);
        smB += __shfl_xor_sync(0xffffffffu, smB, 1);
        smB += __shfl_xor_sync(0xffffffffu, smB, 2);
        lA = lA * aA + smA;
        lB = lB * aB + smB;

        #pragma unroll
        for (int nt = 0; nt < 16; nt++) {
            ofrag[nt][0] *= aA; ofrag[nt][1] *= aA;
            ofrag[nt][2] *= aB; ofrag[nt][3] *= aB;
        }

        #pragma unroll
        for (int nt = 0; nt < 8; nt++) {
            uint32_t pa0 = Psb + (uint32_t)((((m0 + r4) * PS_STRIDE) + nt * 8 + 2 * cc) * 4);
            sts64u(pa0, f2tf32(sfr[nt][0]), f2tf32(sfr[nt][1]));
            sts64u(pa0 + 8 * PS_STRIDE * 4, f2tf32(sfr[nt][2]), f2tf32(sfr[nt][3]));
        }
        __syncwarp();

        #pragma unroll
        for (int kt = 0; kt < 8; kt++) {
            uint32_t afr[4];
            uint32_t pb = Psb + (uint32_t)((((m0 + r4) * PS_STRIDE) + kt * 8 + cc) * 4);
            afr[0] = ldsu(pb);
            afr[1] = ldsu(pb + 8 * PS_STRIDE * 4);
            afr[2] = ldsu(pb + 16);
            afr[3] = ldsu(pb + 8 * PS_STRIDE * 4 + 16);
            #pragma unroll
            for (int nt = 0; nt < 16; nt++) {
                uint32_t vb = Vsb + (uint32_t)((((kt * 8 + cc) * KS_STRIDE) + nt * 8 + r4) * 4);
                uint32_t b0 = ldsu(vb);
                uint32_t b1 = ldsu(vb + 4 * KS_STRIDE * 4);
                uint32_t bfr[2] = { b0, b1 };
                mma_tf32(ofrag[nt], afr, bfr);
            }
        }
    }

    const float iA = 1.f / lA, iB = 1.f / lB;
    #pragma unroll
    for (int nt = 0; nt < 16; nt++) {
        int col = h * HD + nt * 8 + 2 * cc;
        float2 vA, vB;
        vA.x = ofrag[nt][0] * iA; vA.y = ofrag[nt][1] * iA;
        vB.x = ofrag[nt][2] * iB; vB.y = ofrag[nt][3] * iB;
        *(float2*)(O + (size_t)rgA * QDIM + col) = vA;
        *(float2*)(O + (size_t)rgB * QDIM + col) = vB;
    }
}

// ---------------------------------------------------------------------------
extern "C" void kernel_launch(void* const* d_in, const int* in_sizes, int n_in,
                              void* d_out, int out_size)
{
    const float* X    = (const float*)d_in[0];
    const float* cosp = (const float*)d_in[1];
    const float* sinp = (const float*)d_in[2];
    // d_in[3] = attention_mask (causal by construction; applied analytically)
    const float* Wq = (const float*)d_in[4];
    const float* bq = (const float*)d_in[5];
    const float* Wk = (const float*)d_in[6];
    const float* bk = (const float*)d_in[7];
    const float* Wv = (const float*)d_in[8];
    const float* bv = (const float*)d_in[9];
    const float* Wo = (const float*)d_in[10];
    float* out = (float*)d_out;

    float *q, *k, *v, *att, *part;
    cudaGetSymbolAddress((void**)&q, g_q);
    cudaGetSymbolAddress((void**)&k, g_k);
    cudaGetSymbolAddress((void**)&v, g_v);
    cudaGetSymbolAddress((void**)&att, g_att);
    cudaGetSymbolAddress((void**)&part, g_part);

    cudaFuncSetAttribute(tcgemm_tf32, cudaFuncAttributeMaxDynamicSharedMemorySize, GEMM_SMEM);
    cudaFuncSetAttribute(kv_gemm_tf32, cudaFuncAttributeMaxDynamicSharedMemorySize, GEMM_SMEM);
    cudaFuncSetAttribute(flash_attn_tc, cudaFuncAttributeMaxDynamicSharedMemorySize, FA_SMEM);

    // Q projection (tf32 mma.sync)
    tcgemm_tf32<<<dim3(QDIM / 128, S_LEN / 128), 256, GEMM_SMEM>>>(X, Wq, bq, q, S_LEN, QDIM, HIDDEN);

    // Fused K+V projection, split-K=2 -> partials
    kv_gemm_tf32<<<dim3(4, S_LEN / 128, 2), 256, GEMM_SMEM>>>(X, Wk, Wv, part);

    // Reduce + bias + RoPE(K) -> g_k, g_v
    kv_finish<<<(S_LEN * 2 * 16 + 255) / 256, 256>>>(part, bk, bv, cosp, sinp, k, v);

    // RoPE on Q (vectorized)
    rope_q<<<(S_LEN * 16 * 16 + 255) / 256, 256>>>(q, cosp, sinp);

    // Flash attention (tf32 mma.sync)
    flash_attn_tc<<<dim3(S_LEN / 64, NH), 128, FA_SMEM>>>(q, k, v, att);

    // Output projection (tf32 mma.sync) -> d_out
    tcgemm_tf32<<<dim3(QDIM / 128, S_LEN / 128), 256, GEMM_SMEM>>>(att, Wo, nullptr, out, S_LEN, QDIM, HIDDEN);
}

// round 13
// speedup vs baseline: 3.8308x; 1.0059x over previous
#include <cuda_runtime.h>
#include <math.h>
#include <stdint.h>

#define S_LEN 2048
#define HIDDEN 2048
#define NH 16
#define NKV 2
#define HD 128
#define QDIM (NH*HD)    // 2048
#define KVDIM (NKV*HD)  // 256
#define NREP (NH/NKV)   // 8

// Scratch (device globals; no allocation allowed)
__device__ float g_q[S_LEN * QDIM];
__device__ float g_k[S_LEN * KVDIM];
__device__ float g_v[S_LEN * KVDIM];
__device__ float g_att[S_LEN * QDIM];
__device__ float g_part[2 * S_LEN * 512];   // split-K partials for fused KV

// ===========================================================================
// helpers
// ===========================================================================
__device__ __forceinline__ uint32_t smem_to_u32(const void* p) {
    uint32_t a;
    asm("{ .reg .u64 t; cvta.to.shared.u64 t, %1; cvt.u32.u64 %0, t; }" : "=r"(a) : "l"(p));
    return a;
}
__device__ __forceinline__ uint32_t f2tf32(float f) {
    uint32_t r;
    asm("cvt.rna.tf32.f32 %0, %1;" : "=r"(r) : "f"(f));
    return r;
}
__device__ __forceinline__ void sts128u(uint32_t a, uint32_t x, uint32_t y, uint32_t z, uint32_t w) {
    asm volatile("st.shared.v4.b32 [%0], {%1,%2,%3,%4};" :: "r"(a), "r"(x), "r"(y), "r"(z), "r"(w) : "memory");
}
__device__ __forceinline__ void sts64u(uint32_t a, uint32_t x, uint32_t y) {
    asm volatile("st.shared.v2.b32 [%0], {%1,%2};" :: "r"(a), "r"(x), "r"(y) : "memory");
}
__device__ __forceinline__ uint32_t ldsu(uint32_t a) {
    uint32_t v; asm volatile("ld.shared.b32 %0, [%1];" : "=r"(v) : "r"(a)); return v;
}
__device__ __forceinline__ void mma_tf32(float* d, const uint32_t* a, const uint32_t* b) {
    asm volatile("mma.sync.aligned.m16n8k8.row.col.f32.tf32.tf32.f32 "
                 "{%0,%1,%2,%3}, {%4,%5,%6,%7}, {%8,%9}, {%0,%1,%2,%3};"
                 : "+f"(d[0]), "+f"(d[1]), "+f"(d[2]), "+f"(d[3])
                 : "r"(a[0]), "r"(a[1]), "r"(a[2]), "r"(a[3]), "r"(b[0]), "r"(b[1]));
}

// ===========================================================================
// Big-tile tf32 GEMM for Q/O projections: C[M,N] = A[M,K] @ W[K,N] (+bias).
// CTA tile 256x128, BK=32, 256 threads, warp grid 4m x 2n, warp tile 64x64
// (0.5 LDS per HMMA vs 1.5 in the 128x128 version). One wave: 128 CTAs.
// ===========================================================================
#define A2S 36
#define B2S 136
#define A2_BYTES (256 * A2S * 4)      // 36864
#define B2_BYTES (32 * B2S * 4)       // 17408
#define GEMM2_SMEM (2 * (A2_BYTES + B2_BYTES))   // 108544

__global__ __launch_bounds__(256) void tcgemm_big(
    const float* __restrict__ A, const float* __restrict__ W,
    const float* __restrict__ bias, float* __restrict__ C,
    int N, int K)
{
    extern __shared__ float sm[];
    const uint32_t smb = smem_to_u32(sm);
    const uint32_t ASb[2] = { smb, smb + A2_BYTES };
    const uint32_t BSb[2] = { smb + 2 * A2_BYTES, smb + 2 * A2_BYTES + B2_BYTES };

    const int tid = threadIdx.x;
    const int lane = tid & 31, wid = tid >> 5;
    const int wm = wid >> 1, wn = wid & 1;        // 4m x 2n warp grid
    const int r1 = lane >> 2, cc = lane & 3;
    const int row0 = blockIdx.y * 256, col0 = blockIdx.x * 128;
    const int NC = K >> 5;

    const int am = tid >> 3;        // A rows: am + 32t, t<8
    const int kq = tid & 7;
    const int bk = tid >> 5;        // B rows: bk + 8t, t<4
    const int nq = tid & 31;

    float acc[4][8][4];
    #pragma unroll
    for (int mt = 0; mt < 4; mt++)
        #pragma unroll
        for (int nt = 0; nt < 8; nt++)
            #pragma unroll
            for (int i = 0; i < 4; i++) acc[mt][nt][i] = 0.f;

    float4 pa[8], pb[4];

    #define LDG2(c) do { \
        _Pragma("unroll") \
        for (int t = 0; t < 8; t++) \
            pa[t] = *(const float4*)(A + (size_t)(row0 + am + 32 * t) * K + (c) * 32 + kq * 4); \
        _Pragma("unroll") \
        for (int t = 0; t < 4; t++) \
            pb[t] = *(const float4*)(W + (size_t)((c) * 32 + bk + 8 * t) * N + col0 + nq * 4); \
    } while (0)

    #define STS2(buf) do { \
        _Pragma("unroll") \
        for (int t = 0; t < 8; t++) { \
            uint32_t ad = ASb[buf] + (uint32_t)(((am + 32 * t) * A2S + kq * 4) * 4); \
            sts128u(ad, f2tf32(pa[t].x), f2tf32(pa[t].y), f2tf32(pa[t].z), f2tf32(pa[t].w)); \
        } \
        _Pragma("unroll") \
        for (int t = 0; t < 4; t++) { \
            uint32_t bd = BSb[buf] + (uint32_t)(((bk + 8 * t) * B2S + nq * 4) * 4); \
            sts128u(bd, f2tf32(pb[t].x), f2tf32(pb[t].y), f2tf32(pb[t].z), f2tf32(pb[t].w)); \
        } \
    } while (0)

    LDG2(0);
    STS2(0);
    __syncthreads();

    for (int c = 0; c < NC; c++) {
        const int cur = c & 1;
        if (c + 1 < NC) LDG2(c + 1);

        const uint32_t AS = ASb[cur], BS = BSb[cur];
        #pragma unroll
        for (int ks = 0; ks < 4; ks++) {
            uint32_t afr[4][4], bfr[8][2];
            #pragma unroll
            for (int mt = 0; mt < 4; mt++) {
                uint32_t base = AS + (uint32_t)((((wm * 64 + mt * 16 + r1) * A2S) + ks * 8 + cc) * 4);
                afr[mt][0] = ldsu(base);
                afr[mt][1] = ldsu(base + 8 * A2S * 4);
                afr[mt][2] = ldsu(base + 16);
                afr[mt][3] = ldsu(base + 8 * A2S * 4 + 16);
            }
            #pragma unroll
            for (int nt = 0; nt < 8; nt++) {
                uint32_t nb = BS + (uint32_t)((((ks * 8 + cc) * B2S) + wn * 64 + nt * 8 + r1) * 4);
                bfr[nt][0] = ldsu(nb);
                bfr[nt][1] = ldsu(nb + 4 * B2S * 4);
            }
            #pragma unroll
            for (int mt = 0; mt < 4; mt++)
                #pragma unroll
                for (int nt = 0; nt < 8; nt++)
                    mma_tf32(acc[mt][nt], afr[mt], bfr[nt]);
        }

        if (c + 1 < NC) STS2((c + 1) & 1);
        __syncthreads();
    }

    #pragma unroll
    for (int mt = 0; mt < 4; mt++) {
        int r = row0 + wm * 64 + mt * 16 + r1;
        #pragma unroll
        for (int nt = 0; nt < 8; nt++) {
            int col = col0 + wn * 64 + nt * 8 + 2 * cc;
            float bx = 0.f, by = 0.f;
            if (bias) { bx = bias[col]; by = bias[col + 1]; }
            float2 v0, v1;
            v0.x = acc[mt][nt][0] + bx; v0.y = acc[mt][nt][1] + by;
            v1.x = acc[mt][nt][2] + bx; v1.y = acc[mt][nt][3] + by;
            *(float2*)(C + (size_t)r * N + col) = v0;
            *(float2*)(C + (size_t)(r + 8) * N + col) = v1;
        }
    }
    #undef LDG2
    #undef STS2
}

// ===========================================================================
// 128x128 tf32 GEMM machinery (used by fused KV projection).
// ===========================================================================
#define AS_STRIDE 36
#define BS_STRIDE 136
#define AS_BYTES (128 * AS_STRIDE * 4)
#define BS_BYTES (32 * BS_STRIDE * 4)
#define GEMM_SMEM (2 * (AS_BYTES + BS_BYTES))

#define LDG_CHUNK(c, A, W, Kstr, Nstr, bcol0) do { \
    _Pragma("unroll") \
    for (int t = 0; t < 4; t++) \
        pa[t] = *(const float4*)((A) + (size_t)(row0 + am + 32 * t) * (Kstr) + (c) * 32 + kq * 4); \
    _Pragma("unroll") \
    for (int t = 0; t < 4; t++) \
        pb[t] = *(const float4*)((W) + (size_t)((c) * 32 + bk + 8 * t) * (Nstr) + (bcol0) + nq * 4); \
} while (0)

#define STS_CHUNK(buf) do { \
    _Pragma("unroll") \
    for (int t = 0; t < 4; t++) { \
        uint32_t ad = ASb[buf] + (uint32_t)(((am + 32 * t) * AS_STRIDE + kq * 4) * 4); \
        sts128u(ad, f2tf32(pa[t].x), f2tf32(pa[t].y), f2tf32(pa[t].z), f2tf32(pa[t].w)); \
    } \
    _Pragma("unroll") \
    for (int t = 0; t < 4; t++) { \
        uint32_t bd = BSb[buf] + (uint32_t)(((bk + 8 * t) * BS_STRIDE + nq * 4) * 4); \
        sts128u(bd, f2tf32(pb[t].x), f2tf32(pb[t].y), f2tf32(pb[t].z), f2tf32(pb[t].w)); \
    } \
} while (0)

#define GEMM_COMPUTE(cur) do { \
    const uint32_t AS = ASb[cur], BS = BSb[cur]; \
    _Pragma("unroll") \
    for (int ks = 0; ks < 4; ks++) { \
        uint32_t afr[4][4], bfr[4][2]; \
        _Pragma("unroll") \
        for (int mt = 0; mt < 4; mt++) { \
            uint32_t base = AS + (uint32_t)((((wm * 64 + mt * 16 + r1) * AS_STRIDE) + ks * 8 + cc) * 4); \
            afr[mt][0] = ldsu(base); \
            afr[mt][1] = ldsu(base + 8 * AS_STRIDE * 4); \
            afr[mt][2] = ldsu(base + 16); \
            afr[mt][3] = ldsu(base + 8 * AS_STRIDE * 4 + 16); \
        } \
        _Pragma("unroll") \
        for (int nt = 0; nt < 4; nt++) { \
            uint32_t nb = BS + (uint32_t)((((ks * 8 + cc) * BS_STRIDE) + wn * 32 + nt * 8 + r1) * 4); \
            bfr[nt][0] = ldsu(nb); \
            bfr[nt][1] = ldsu(nb + 4 * BS_STRIDE * 4); \
        } \
        _Pragma("unroll") \
        for (int mt = 0; mt < 4; mt++) \
            _Pragma("unroll") \
            for (int nt = 0; nt < 4; nt++) \
                mma_tf32(acc[mt][nt], afr[mt], bfr[nt]); \
    } \
} while (0)

// ===========================================================================
// Fused K+V projection with split-K=2 (unchanged from R8).
// ===========================================================================
__global__ __launch_bounds__(256) void kv_gemm_tf32(
    const float* __restrict__ A, const float* __restrict__ Wk,
    const float* __restrict__ Wv, float* __restrict__ Cpart)
{
    extern __shared__ float sm[];
    const uint32_t smb = smem_to_u32(sm);
    const uint32_t ASb[2] = { smb, smb + AS_BYTES };
    const uint32_t BSb[2] = { smb + 2 * AS_BYTES, smb + 2 * AS_BYTES + BS_BYTES };

    const int tid = threadIdx.x;
    const int lane = tid & 31, wid = tid >> 5;
    const int wm = wid & 1, wn = wid >> 1;
    const int r1 = lane >> 2, cc = lane & 3;
    const int row0 = blockIdx.y * 128;
    const int fcol0 = blockIdx.x * 128;
    const float* W = (blockIdx.x < 2) ? Wk : Wv;
    const int bcol0 = (blockIdx.x & 1) * 128;
    const int cbase = blockIdx.z * 32;
    float* C = Cpart + (size_t)blockIdx.z * S_LEN * 512;

    const int am = tid >> 3;
    const int kq = tid & 7;
    const int bk = tid >> 5;
    const int nq = tid & 31;

    float acc[4][4][4];
    #pragma unroll
    for (int mt = 0; mt < 4; mt++)
        #pragma unroll
        for (int nt = 0; nt < 4; nt++)
            #pragma unroll
            for (int i = 0; i < 4; i++) acc[mt][nt][i] = 0.f;

    float4 pa[4], pb[4];

    LDG_CHUNK(cbase, A, W, HIDDEN, KVDIM, bcol0);
    STS_CHUNK(0);
    __syncthreads();

    for (int c = 0; c < 32; c++) {
        const int cur = c & 1;
        if (c + 1 < 32) LDG_CHUNK(cbase + c + 1, A, W, HIDDEN, KVDIM, bcol0);
        GEMM_COMPUTE(cur);
        if (c + 1 < 32) STS_CHUNK((c + 1) & 1);
        __syncthreads();
    }

    #pragma unroll
    for (int mt = 0; mt < 4; mt++) {
        int r = row0 + wm * 64 + mt * 16 + r1;
        #pragma unroll
        for (int nt = 0; nt < 4; nt++) {
            int col = fcol0 + wn * 32 + nt * 8 + 2 * cc;
            float2 v0, v1;
            v0.x = acc[mt][nt][0]; v0.y = acc[mt][nt][1];
            v1.x = acc[mt][nt][2]; v1.y = acc[mt][nt][3];
            *(float2*)(C + (size_t)r * 512 + col) = v0;
            *(float2*)(C + (size_t)(r + 8) * 512 + col) = v1;
        }
    }
}

// ===========================================================================
// KV finisher: reduce split-K partials + bias; RoPE for K (unchanged).
// ===========================================================================
__global__ __launch_bounds__(256) void kv_finish(
    const float* __restrict__ part, const float* __restrict__ bkb,
    const float* __restrict__ bvb, const float* __restrict__ cosp,
    const float* __restrict__ sinp, float* __restrict__ Kout,
    float* __restrict__ Vout)
{
    int idx = blockIdx.x * blockDim.x + threadIdx.x;
    int d4 = (idx & 15) * 4;
    int kh = (idx >> 4) & 1;
    int s  = idx >> 5;
    if (s >= S_LEN) return;

    const size_t rbase = (size_t)s * 512;
    const size_t pz = (size_t)S_LEN * 512;
    int kc = kh * HD;

    float4 klo = *(const float4*)(part + rbase + kc + d4);
    float4 khi = *(const float4*)(part + rbase + kc + 64 + d4);
    float4 klo2 = *(const float4*)(part + pz + rbase + kc + d4);
    float4 khi2 = *(const float4*)(part + pz + rbase + kc + 64 + d4);
    klo.x += klo2.x; klo.y += klo2.y; klo.z += klo2.z; klo.w += klo2.w;
    khi.x += khi2.x; khi.y += khi2.y; khi.z += khi2.z; khi.w += khi2.w;
    float4 bl = *(const float4*)(bkb + kc + d4);
    float4 bh = *(const float4*)(bkb + kc + 64 + d4);
    klo.x += bl.x; klo.y += bl.y; klo.z += bl.z; klo.w += bl.w;
    khi.x += bh.x; khi.y += bh.y; khi.z += bh.z; khi.w += bh.w;

    float4 c1 = *(const float4*)(cosp + s * HD + d4);
    float4 s1 = *(const float4*)(sinp + s * HD + d4);
    float4 c2 = *(const float4*)(cosp + s * HD + 64 + d4);
    float4 s2 = *(const float4*)(sinp + s * HD + 64 + d4);

    float4 rlo, rhi;
    rlo.x = klo.x * c1.x - khi.x * s1.x;
    rlo.y = klo.y * c1.y - khi.y * s1.y;
    rlo.z = klo.z * c1.z - khi.z * s1.z;
    rlo.w = klo.w * c1.w - khi.w * s1.w;
    rhi.x = khi.x * c2.x + klo.x * s2.x;
    rhi.y = khi.y * c2.y + klo.y * s2.y;
    rhi.z = khi.z * c2.z + klo.z * s2.z;
    rhi.w = khi.w * c2.w + klo.w * s2.w;

    *(float4*)(Kout + (size_t)s * KVDIM + kc + d4) = rlo;
    *(float4*)(Kout + (size_t)s * KVDIM + kc + 64 + d4) = rhi;

    float4 vlo = *(const float4*)(part + rbase + 256 + kc + d4);
    float4 vhi = *(const float4*)(part + rbase + 256 + kc + 64 + d4);
    float4 vlo2 = *(const float4*)(part + pz + rbase + 256 + kc + d4);
    float4 vhi2 = *(const float4*)(part + pz + rbase + 256 + kc + 64 + d4);
    float4 vbl = *(const float4*)(bvb + kc + d4);
    float4 vbh = *(const float4*)(bvb + kc + 64 + d4);
    vlo.x += vlo2.x + vbl.x; vlo.y += vlo2.y + vbl.y;
    vlo.z += vlo2.z + vbl.z; vlo.w += vlo2.w + vbl.w;
    vhi.x += vhi2.x + vbh.x; vhi.y += vhi2.y + vbh.y;
    vhi.z += vhi2.z + vbh.z; vhi.w += vhi2.w + vbh.w;

    *(float4*)(Vout + (size_t)s * KVDIM + kc + d4) = vlo;
    *(float4*)(Vout + (size_t)s * KVDIM + kc + 64 + d4) = vhi;
}

// ---------------------------------------------------------------------------
// RoPE for Q (unchanged).
// ---------------------------------------------------------------------------
__global__ __launch_bounds__(256) void rope_q(
    float* __restrict__ x, const float* __restrict__ cosp,
    const float* __restrict__ sinp)
{
    int idx = blockIdx.x * blockDim.x + threadIdx.x;
    int d4 = (idx & 15) * 4;
    int hh = (idx >> 4) & 15;
    int s  = idx >> 8;
    if (s >= S_LEN) return;
    size_t b = (size_t)s * QDIM + hh * HD;

    float4 x1 = *(float4*)(x + b + d4);
    float4 x2 = *(float4*)(x + b + 64 + d4);
    float4 c1 = *(const float4*)(cosp + s * HD + d4);
    float4 s1 = *(const float4*)(sinp + s * HD + d4);
    float4 c2 = *(const float4*)(cosp + s * HD + 64 + d4);
    float4 s2 = *(const float4*)(sinp + s * HD + 64 + d4);

    float4 r1v, r2v;
    r1v.x = x1.x * c1.x - x2.x * s1.x;
    r1v.y = x1.y * c1.y - x2.y * s1.y;
    r1v.z = x1.z * c1.z - x2.z * s1.z;
    r1v.w = x1.w * c1.w - x2.w * s1.w;
    r2v.x = x2.x * c2.x + x1.x * s2.x;
    r2v.y = x2.y * c2.y + x1.y * s2.y;
    r2v.z = x2.z * c2.z + x1.z * s2.z;
    r2v.w = x2.w * c2.w + x1.w * s2.w;

    *(float4*)(x + b + d4) = r1v;
    *(float4*)(x + b + 64 + d4) = r2v;
}

// ===========================================================================
// Flash attention, tf32 mma.sync (unchanged from R4/R8).
// ===========================================================================
#define KS_STRIDE 132
#define PS_STRIDE 68
#define FA_SMEM ((2 * 64 * KS_STRIDE + 64 * PS_STRIDE) * 4)

__global__ __launch_bounds__(128) void flash_attn_tc(
    const float* __restrict__ Q, const float* __restrict__ Kp,
    const float* __restrict__ Vp, float* __restrict__ O)
{
    extern __shared__ float smf[];
    const uint32_t Ksb = smem_to_u32(smf);
    const uint32_t Vsb = Ksb + 64 * KS_STRIDE * 4;
    const uint32_t Psb = Vsb + 64 * KS_STRIDE * 4;

    const int qb = gridDim.x - 1 - blockIdx.x;
    const int h = blockIdx.y;
    const int kvh = h / NREP;
    const int tid = threadIdx.x;
    const int lane = tid & 31, wid = tid >> 5;
    const int r4 = lane >> 2, cc = lane & 3;
    const int q0 = qb * 64;
    const int m0 = wid * 16;
    const float scale = 0.08838834764831845f;

    uint32_t qfrag[16][4];
    {
        const float* qA = Q + (size_t)(q0 + m0 + r4) * QDIM + h * HD;
        const float* qB = qA + 8 * QDIM;
        #pragma unroll
        for (int kt = 0; kt < 16; kt++) {
            qfrag[kt][0] = f2tf32(qA[kt * 8 + cc]);
            qfrag[kt][1] = f2tf32(qB[kt * 8 + cc]);
            qfrag[kt][2] = f2tf32(qA[kt * 8 + cc + 4]);
            qfrag[kt][3] = f2tf32(qB[kt * 8 + cc + 4]);
        }
    }

    float mA = -1e30f, mB = -1e30f, lA = 0.f, lB = 0.f;
    float ofrag[16][4];
    #pragma unroll
    for (int nt = 0; nt < 16; nt++)
        #pragma unroll
        for (int j = 0; j < 4; j++) ofrag[nt][j] = 0.f;

    const int rgA = q0 + m0 + r4;
    const int rgB = rgA + 8;

    for (int kb = 0; kb <= qb; kb++) {
        const int k0 = kb * 64;
        __syncthreads();
        #pragma unroll
        for (int t = 0; t < 16; t++) {
            int i = tid + t * 128;
            int r = i >> 5, c4 = (i & 31) * 4;
            size_t goff = (size_t)(k0 + r) * KVDIM + kvh * HD + c4;
            float4 kv = *(const float4*)(Kp + goff);
            float4 vv = *(const float4*)(Vp + goff);
            uint32_t soff = (uint32_t)((r * KS_STRIDE + c4) * 4);
            sts128u(Ksb + soff, f2tf32(kv.x), f2tf32(kv.y), f2tf32(kv.z), f2tf32(kv.w));
            sts128u(Vsb + soff, f2tf32(vv.x), f2tf32(vv.y), f2tf32(vv.z), f2tf32(vv.w));
        }
        __syncthreads();

        float sfr[8][4];
        #pragma unroll
        for (int nt = 0; nt < 8; nt++)
            #pragma unroll
            for (int j = 0; j < 4; j++) sfr[nt][j] = 0.f;

        #pragma unroll
        for (int kt = 0; kt < 16; kt++) {
            uint32_t bfr[8][2];
            #pragma unroll
            for (int nt = 0; nt < 8; nt++) {
                uint32_t ba = Ksb + (uint32_t)((((nt * 8 + r4) * KS_STRIDE) + kt * 8 + cc) * 4);
                bfr[nt][0] = ldsu(ba);
                bfr[nt][1] = ldsu(ba + 16);
            }
            #pragma unroll
            for (int nt = 0; nt < 8; nt++)
                mma_tf32(sfr[nt], qfrag[kt], bfr[nt]);
        }

        const bool diag = (kb == qb);
        #pragma unroll
        for (int nt = 0; nt < 8; nt++) {
            int cg = k0 + nt * 8 + 2 * cc;
            sfr[nt][0] *= scale; sfr[nt][1] *= scale;
            sfr[nt][2] *= scale; sfr[nt][3] *= scale;
            if (diag) {
                if (cg     > rgA) sfr[nt][0] = -1e30f;
                if (cg + 1 > rgA) sfr[nt][1] = -1e30f;
                if (cg     > rgB) sfr[nt][2] = -1e30f;
                if (cg + 1 > rgB) sfr[nt][3] = -1e30f;
            }
        }

        float rmA = -1e30f, rmB = -1e30f;
        #pragma unroll
        for (int nt = 0; nt < 8; nt++) {
            rmA = fmaxf(rmA, fmaxf(sfr[nt][0], sfr[nt][1]));
            rmB = fmaxf(rmB, fmaxf(sfr[nt][2], sfr[nt][3]));
        }
        rmA = fmaxf(rmA, __shfl_xor_sync(0xffffffffu, rmA, 1));
        rmA = fmaxf(rmA, __shfl_xor_sync(0xffffffffu, rmA, 2));
        rmB = fmaxf(rmB, __shfl_xor_sync(0xffffffffu, rmB, 1));
        rmB = fmaxf(rmB, __shfl_xor_sync(0xffffffffu, rmB, 2));

        float mnA = fmaxf(mA, rmA), mnB = fmaxf(mB, rmB);
        float aA = __expf(mA - mnA), aB = __expf(mB - mnB);
        mA = mnA; mB = mnB;

        float smA = 0.f, smB = 0.f;
        #pragma unroll
        for (int nt = 0; nt < 8; nt++) {
            sfr[nt][0] = __expf(sfr[nt][0] - mnA);
            sfr[nt][1] = __expf(sfr[nt][1] - mnA);
            sfr[nt][2] = __expf(sfr[nt][2] - mnB);
            sfr[nt][3] = __expf(sfr[nt][3] - mnB);
            smA += sfr[nt][0] + sfr[nt][1];
            smB += sfr[nt][2] + sfr[nt][3];
        }
        smA += __shfl_xor_sync(0xffffffffu, smA, 1);
        smA += __shfl_xor_sync(0xffffffffu, smA, 2);
        smB += __shfl_xor_sync(0xffffffffu, smB, 1);
        smB += __shfl_xor_sync(0xffffffffu, smB, 2);
        lA = lA * aA + smA;
        lB = lB * aB + smB;

        #pragma unroll
        for (int nt = 0; nt < 16; nt++) {
            ofrag[nt][0] *= aA; ofrag[nt][1] *= aA;
            ofrag[nt][2] *= aB; ofrag[nt][3] *= aB;
        }

        #pragma unroll
        for (int nt = 0; nt < 8; nt++) {
            uint32_t pa0 = Psb + (uint32_t)((((m0 + r4) * PS_STRIDE) + nt * 8 + 2 * cc) * 4);
            sts64u(pa0, f2tf32(sfr[nt][0]), f2tf32(sfr[nt][1]));
            sts64u(pa0 + 8 * PS_STRIDE * 4, f2tf32(sfr[nt][2]), f2tf32(sfr[nt][3]));
        }
        __syncwarp();

        #pragma unroll
        for (int kt = 0; kt < 8; kt++) {
            uint32_t afr[4];
            uint32_t pb = Psb + (uint32_t)((((m0 + r4) * PS_STRIDE) + kt * 8 + cc) * 4);
            afr[0] = ldsu(pb);
            afr[1] = ldsu(pb + 8 * PS_STRIDE * 4);
            afr[2] = ldsu(pb + 16);
            afr[3] = ldsu(pb + 8 * PS_STRIDE * 4 + 16);
            #pragma unroll
            for (int nt = 0; nt < 16; nt++) {
                uint32_t vb = Vsb + (uint32_t)((((kt * 8 + cc) * KS_STRIDE) + nt * 8 + r4) * 4);
                uint32_t b0 = ldsu(vb);
                uint32_t b1 = ldsu(vb + 4 * KS_STRIDE * 4);
                uint32_t bfr[2] = { b0, b1 };
                mma_tf32(ofrag[nt], afr, bfr);
            }
        }
    }

    const float iA = 1.f / lA, iB = 1.f / lB;
    #pragma unroll
    for (int nt = 0; nt < 16; nt++) {
        int col = h * HD + nt * 8 + 2 * cc;
        float2 vA, vB;
        vA.x = ofrag[nt][0] * iA; vA.y = ofrag[nt][1] * iA;
        vB.x = ofrag[nt][2] * iB; vB.y = ofrag[nt][3] * iB;
        *(float2*)(O + (size_t)rgA * QDIM + col) = vA;
        *(float2*)(O + (size_t)rgB * QDIM + col) = vB;
    }
}

// ---------------------------------------------------------------------------
extern "C" void kernel_launch(void* const* d_in, const int* in_sizes, int n_in,
                              void* d_out, int out_size)
{
    const float* X    = (const float*)d_in[0];
    const float* cosp = (const float*)d_in[1];
    const float* sinp = (const float*)d_in[2];
    // d_in[3] = attention_mask (causal by construction; applied analytically)
    const float* Wq = (const float*)d_in[4];
    const float* bq = (const float*)d_in[5];
    const float* Wk = (const float*)d_in[6];
    const float* bk = (const float*)d_in[7];
    const float* Wv = (const float*)d_in[8];
    const float* bv = (const float*)d_in[9];
    const float* Wo = (const float*)d_in[10];
    float* out = (float*)d_out;

    float *q, *k, *v, *att, *part;
    cudaGetSymbolAddress((void**)&q, g_q);
    cudaGetSymbolAddress((void**)&k, g_k);
    cudaGetSymbolAddress((void**)&v, g_v);
    cudaGetSymbolAddress((void**)&att, g_att);
    cudaGetSymbolAddress((void**)&part, g_part);

    cudaFuncSetAttribute(tcgemm_big, cudaFuncAttributeMaxDynamicSharedMemorySize, GEMM2_SMEM);
    cudaFuncSetAttribute(kv_gemm_tf32, cudaFuncAttributeMaxDynamicSharedMemorySize, GEMM_SMEM);
    cudaFuncSetAttribute(flash_attn_tc, cudaFuncAttributeMaxDynamicSharedMemorySize, FA_SMEM);

    // Q projection (256x128-tile tf32 mma.sync, one wave)
    tcgemm_big<<<dim3(QDIM / 128, S_LEN / 256), 256, GEMM2_SMEM>>>(X, Wq, bq, q, QDIM, HIDDEN);

    // Fused K+V projection, split-K=2 -> partials
    kv_gemm_tf32<<<dim3(4, S_LEN / 128, 2), 256, GEMM_SMEM>>>(X, Wk, Wv, part);

    // Reduce + bias + RoPE(K) -> g_k, g_v
    kv_finish<<<(S_LEN * 2 * 16 + 255) / 256, 256>>>(part, bk, bv, cosp, sinp, k, v);

    // RoPE on Q (vectorized)
    rope_q<<<(S_LEN * 16 * 16 + 255) / 256, 256>>>(q, cosp, sinp);

    // Flash attention (tf32 mma.sync)
    flash_attn_tc<<<dim3(S_LEN / 64, NH), 128, FA_SMEM>>>(q, k, v, att);

    // Output projection (256x128-tile tf32 mma.sync) -> d_out
    tcgemm_big<<<dim3(QDIM / 128, S_LEN / 256), 256, GEMM2_SMEM>>>(att, Wo, nullptr, out, QDIM, HIDDEN);
}

// round 15
// speedup vs baseline: 4.1394x; 1.0806x over previous
#include <cuda_runtime.h>
#include <math.h>
#include <stdint.h>

#define S_LEN 2048
#define HIDDEN 2048
#define NH 16
#define NKV 2
#define HD 128
#define QDIM (NH*HD)    // 2048
#define KVDIM (NKV*HD)  // 256
#define NREP (NH/NKV)   // 8

// Scratch (device globals; no allocation allowed)
__device__ float g_q[S_LEN * QDIM];
__device__ float g_k[S_LEN * KVDIM];
__device__ float g_v[S_LEN * KVDIM];
__device__ float g_att[S_LEN * QDIM];
__device__ float g_part[2 * S_LEN * 512];   // split-K partials for fused KV

// ===========================================================================
// helpers
// ===========================================================================
__device__ __forceinline__ uint32_t smem_to_u32(const void* p) {
    uint32_t a;
    asm("{ .reg .u64 t; cvta.to.shared.u64 t, %1; cvt.u32.u64 %0, t; }" : "=r"(a) : "l"(p));
    return a;
}
__device__ __forceinline__ uint32_t f2tf32(float f) {
    uint32_t r;
    asm("cvt.rna.tf32.f32 %0, %1;" : "=r"(r) : "f"(f));
    return r;
}
__device__ __forceinline__ void sts128u(uint32_t a, uint32_t x, uint32_t y, uint32_t z, uint32_t w) {
    asm volatile("st.shared.v4.b32 [%0], {%1,%2,%3,%4};" :: "r"(a), "r"(x), "r"(y), "r"(z), "r"(w) : "memory");
}
__device__ __forceinline__ void sts64u(uint32_t a, uint32_t x, uint32_t y) {
    asm volatile("st.shared.v2.b32 [%0], {%1,%2};" :: "r"(a), "r"(x), "r"(y) : "memory");
}
__device__ __forceinline__ uint32_t ldsu(uint32_t a) {
    uint32_t v; asm volatile("ld.shared.b32 %0, [%1];" : "=r"(v) : "r"(a)); return v;
}
// tf32-rounded load: fragment fp32 bits from smem, then RNA-round to tf32.
__device__ __forceinline__ uint32_t ldsu_tf32(uint32_t a) {
    return f2tf32(__uint_as_float(ldsu(a)));
}
__device__ __forceinline__ void mma_tf32(float* d, const uint32_t* a, const uint32_t* b) {
    asm volatile("mma.sync.aligned.m16n8k8.row.col.f32.tf32.tf32.f32 "
                 "{%0,%1,%2,%3}, {%4,%5,%6,%7}, {%8,%9}, {%0,%1,%2,%3};"
                 : "+f"(d[0]), "+f"(d[1]), "+f"(d[2]), "+f"(d[3])
                 : "r"(a[0]), "r"(a[1]), "r"(a[2]), "r"(a[3]), "r"(b[0]), "r"(b[1]));
}
__device__ __forceinline__ void cpasync16(uint32_t saddr, const void* gaddr) {
    asm volatile("cp.async.cg.shared.global [%0], [%1], 16;" :: "r"(saddr), "l"(gaddr) : "memory");
}
#define CP_COMMIT() asm volatile("cp.async.commit_group;" ::: "memory")
#define CP_WAIT2()  asm volatile("cp.async.wait_group 2;" ::: "memory")

// ===========================================================================
// Big-tile tf32 GEMM for Q/O projections: C[M,N] = A[M,K] @ W[K,N] (+bias).
// CTA tile 256x128, BK=32, 256 threads, warp grid 4m x 2n, warp tile 64x64.
// cp.async 3-stage pipeline (raw fp32 in smem; RNA tf32 rounding applied at
// fragment-load time so numerics match the STS-time-converted path exactly).
// One wave: 128 CTAs.
// ===========================================================================
#define A2S 36
#define B2S 136
#define A2_BYTES (256 * A2S * 4)            // 36864
#define B2_BYTES (32 * B2S * 4)             // 17408
#define STAGE_BYTES (A2_BYTES + B2_BYTES)   // 54272
#define GEMM2_SMEM (3 * STAGE_BYTES)        // 162816

__global__ __launch_bounds__(256) void tcgemm_big(
    const float* __restrict__ A, const float* __restrict__ W,
    const float* __restrict__ bias, float* __restrict__ C,
    int N, int K)
{
    extern __shared__ float sm[];
    const uint32_t smb = smem_to_u32(sm);
    uint32_t ASb[3], BSb[3];
    #pragma unroll
    for (int s = 0; s < 3; s++) {
        ASb[s] = smb + s * STAGE_BYTES;
        BSb[s] = ASb[s] + A2_BYTES;
    }

    const int tid = threadIdx.x;
    const int lane = tid & 31, wid = tid >> 5;
    const int wm = wid >> 1, wn = wid & 1;        // 4m x 2n warp grid
    const int r1 = lane >> 2, cc = lane & 3;
    const int row0 = blockIdx.y * 256, col0 = blockIdx.x * 128;
    const int NC = K >> 5;

    const int am = tid >> 3;        // A rows: am + 32t, t<8
    const int kq = tid & 7;
    const int bk = tid >> 5;        // B rows: bk + 8t, t<4
    const int nq = tid & 31;

    float acc[4][8][4];
    #pragma unroll
    for (int mt = 0; mt < 4; mt++)
        #pragma unroll
        for (int nt = 0; nt < 8; nt++)
            #pragma unroll
            for (int i = 0; i < 4; i++) acc[mt][nt][i] = 0.f;

    #define ISSUE2(c, buf) do { \
        _Pragma("unroll") \
        for (int t = 0; t < 8; t++) \
            cpasync16(ASb[buf] + (uint32_t)(((am + 32 * t) * A2S + kq * 4) * 4), \
                      A + (size_t)(row0 + am + 32 * t) * K + (c) * 32 + kq * 4); \
        _Pragma("unroll") \
        for (int t = 0; t < 4; t++) \
            cpasync16(BSb[buf] + (uint32_t)(((bk + 8 * t) * B2S + nq * 4) * 4), \
                      W + (size_t)((c) * 32 + bk + 8 * t) * N + col0 + nq * 4); \
    } while (0)

    // prologue: fill 3 stages
    #pragma unroll
    for (int s = 0; s < 3; s++) {
        if (s < NC) ISSUE2(s, s);
        CP_COMMIT();
    }

    int buf = 0;
    for (int c = 0; c < NC; c++) {
        CP_WAIT2();
        __syncthreads();

        const uint32_t AS = ASb[buf], BS = BSb[buf];
        #pragma unroll
        for (int ks = 0; ks < 4; ks++) {
            uint32_t afr[4][4], bfr[8][2];
            #pragma unroll
            for (int mt = 0; mt < 4; mt++) {
                uint32_t base = AS + (uint32_t)((((wm * 64 + mt * 16 + r1) * A2S) + ks * 8 + cc) * 4);
                afr[mt][0] = ldsu_tf32(base);
                afr[mt][1] = ldsu_tf32(base + 8 * A2S * 4);
                afr[mt][2] = ldsu_tf32(base + 16);
                afr[mt][3] = ldsu_tf32(base + 8 * A2S * 4 + 16);
            }
            #pragma unroll
            for (int nt = 0; nt < 8; nt++) {
                uint32_t nb = BS + (uint32_t)((((ks * 8 + cc) * B2S) + wn * 64 + nt * 8 + r1) * 4);
                bfr[nt][0] = ldsu_tf32(nb);
                bfr[nt][1] = ldsu_tf32(nb + 4 * B2S * 4);
            }
            #pragma unroll
            for (int mt = 0; mt < 4; mt++)
                #pragma unroll
                for (int nt = 0; nt < 8; nt++)
                    mma_tf32(acc[mt][nt], afr[mt], bfr[nt]);
        }

        __syncthreads();   // all warps done reading buf before refill
        if (c + 3 < NC) ISSUE2(c + 3, buf);
        CP_COMMIT();
        buf = (buf + 1 == 3) ? 0 : buf + 1;
    }
    #undef ISSUE2

    #pragma unroll
    for (int mt = 0; mt < 4; mt++) {
        int r = row0 + wm * 64 + mt * 16 + r1;
        #pragma unroll
        for (int nt = 0; nt < 8; nt++) {
            int col = col0 + wn * 64 + nt * 8 + 2 * cc;
            float bx = 0.f, by = 0.f;
            if (bias) { bx = bias[col]; by = bias[col + 1]; }
            float2 v0, v1;
            v0.x = acc[mt][nt][0] + bx; v0.y = acc[mt][nt][1] + by;
            v1.x = acc[mt][nt][2] + bx; v1.y = acc[mt][nt][3] + by;
            *(float2*)(C + (size_t)r * N + col) = v0;
            *(float2*)(C + (size_t)(r + 8) * N + col) = v1;
        }
    }
}

// ===========================================================================
// 128x128 tf32 GEMM machinery (used by fused KV projection; unchanged).
// ===========================================================================
#define AS_STRIDE 36
#define BS_STRIDE 136
#define AS_BYTES (128 * AS_STRIDE * 4)
#define BS_BYTES (32 * BS_STRIDE * 4)
#define GEMM_SMEM (2 * (AS_BYTES + BS_BYTES))

#define LDG_CHUNK(c, A, W, Kstr, Nstr, bcol0) do { \
    _Pragma("unroll") \
    for (int t = 0; t < 4; t++) \
        pa[t] = *(const float4*)((A) + (size_t)(row0 + am + 32 * t) * (Kstr) + (c) * 32 + kq * 4); \
    _Pragma("unroll") \
    for (int t = 0; t < 4; t++) \
        pb[t] = *(const float4*)((W) + (size_t)((c) * 32 + bk + 8 * t) * (Nstr) + (bcol0) + nq * 4); \
} while (0)

#define STS_CHUNK(buf) do { \
    _Pragma("unroll") \
    for (int t = 0; t < 4; t++) { \
        uint32_t ad = ASb[buf] + (uint32_t)(((am + 32 * t) * AS_STRIDE + kq * 4) * 4); \
        sts128u(ad, f2tf32(pa[t].x), f2tf32(pa[t].y), f2tf32(pa[t].z), f2tf32(pa[t].w)); \
    } \
    _Pragma("unroll") \
    for (int t = 0; t < 4; t++) { \
        uint32_t bd = BSb[buf] + (uint32_t)(((bk + 8 * t) * BS_STRIDE + nq * 4) * 4); \
        sts128u(bd, f2tf32(pb[t].x), f2tf32(pb[t].y), f2tf32(pb[t].z), f2tf32(pb[t].w)); \
    } \
} while (0)

#define GEMM_COMPUTE(cur) do { \
    const uint32_t AS = ASb[cur], BS = BSb[cur]; \
    _Pragma("unroll") \
    for (int ks = 0; ks < 4; ks++) { \
        uint32_t afr[4][4], bfr[4][2]; \
        _Pragma("unroll") \
        for (int mt = 0; mt < 4; mt++) { \
            uint32_t base = AS + (uint32_t)((((wm * 64 + mt * 16 + r1) * AS_STRIDE) + ks * 8 + cc) * 4); \
            afr[mt][0] = ldsu(base); \
            afr[mt][1] = ldsu(base + 8 * AS_STRIDE * 4); \
            afr[mt][2] = ldsu(base + 16); \
            afr[mt][3] = ldsu(base + 8 * AS_STRIDE * 4 + 16); \
        } \
        _Pragma("unroll") \
        for (int nt = 0; nt < 4; nt++) { \
            uint32_t nb = BS + (uint32_t)((((ks * 8 + cc) * BS_STRIDE) + wn * 32 + nt * 8 + r1) * 4); \
            bfr[nt][0] = ldsu(nb); \
            bfr[nt][1] = ldsu(nb + 4 * BS_STRIDE * 4); \
        } \
        _Pragma("unroll") \
        for (int mt = 0; mt < 4; mt++) \
            _Pragma("unroll") \
            for (int nt = 0; nt < 4; nt++) \
                mma_tf32(acc[mt][nt], afr[mt], bfr[nt]); \
    } \
} while (0)

// ===========================================================================
// Fused K+V projection with split-K=2 (unchanged from R8).
// ===========================================================================
__global__ __launch_bounds__(256) void kv_gemm_tf32(
    const float* __restrict__ A, const float* __restrict__ Wk,
    const float* __restrict__ Wv, float* __restrict__ Cpart)
{
    extern __shared__ float sm[];
    const uint32_t smb = smem_to_u32(sm);
    const uint32_t ASb[2] = { smb, smb + AS_BYTES };
    const uint32_t BSb[2] = { smb + 2 * AS_BYTES, smb + 2 * AS_BYTES + BS_BYTES };

    const int tid = threadIdx.x;
    const int lane = tid & 31, wid = tid >> 5;
    const int wm = wid & 1, wn = wid >> 1;
    const int r1 = lane >> 2, cc = lane & 3;
    const int row0 = blockIdx.y * 128;
    const int fcol0 = blockIdx.x * 128;
    const float* W = (blockIdx.x < 2) ? Wk : Wv;
    const int bcol0 = (blockIdx.x & 1) * 128;
    const int cbase = blockIdx.z * 32;
    float* C = Cpart + (size_t)blockIdx.z * S_LEN * 512;

    const int am = tid >> 3;
    const int kq = tid & 7;
    const int bk = tid >> 5;
    const int nq = tid & 31;

    float acc[4][4][4];
    #pragma unroll
    for (int mt = 0; mt < 4; mt++)
        #pragma unroll
        for (int nt = 0; nt < 4; nt++)
            #pragma unroll
            for (int i = 0; i < 4; i++) acc[mt][nt][i] = 0.f;

    float4 pa[4], pb[4];

    LDG_CHUNK(cbase, A, W, HIDDEN, KVDIM, bcol0);
    STS_CHUNK(0);
    __syncthreads();

    for (int c = 0; c < 32; c++) {
        const int cur = c & 1;
        if (c + 1 < 32) LDG_CHUNK(cbase + c + 1, A, W, HIDDEN, KVDIM, bcol0);
        GEMM_COMPUTE(cur);
        if (c + 1 < 32) STS_CHUNK((c + 1) & 1);
        __syncthreads();
    }

    #pragma unroll
    for (int mt = 0; mt < 4; mt++) {
        int r = row0 + wm * 64 + mt * 16 + r1;
        #pragma unroll
        for (int nt = 0; nt < 4; nt++) {
            int col = fcol0 + wn * 32 + nt * 8 + 2 * cc;
            float2 v0, v1;
            v0.x = acc[mt][nt][0]; v0.y = acc[mt][nt][1];
            v1.x = acc[mt][nt][2]; v1.y = acc[mt][nt][3];
            *(float2*)(C + (size_t)r * 512 + col) = v0;
            *(float2*)(C + (size_t)(r + 8) * 512 + col) = v1;
        }
    }
}

// ===========================================================================
// KV finisher: reduce split-K partials + bias; RoPE for K (unchanged).
// ===========================================================================
__global__ __launch_bounds__(256) void kv_finish(
    const float* __restrict__ part, const float* __restrict__ bkb,
    const float* __restrict__ bvb, const float* __restrict__ cosp,
    const float* __restrict__ sinp, float* __restrict__ Kout,
    float* __restrict__ Vout)
{
    int idx = blockIdx.x * blockDim.x + threadIdx.x;
    int d4 = (idx & 15) * 4;
    int kh = (idx >> 4) & 1;
    int s  = idx >> 5;
    if (s >= S_LEN) return;

    const size_t rbase = (size_t)s * 512;
    const size_t pz = (size_t)S_LEN * 512;
    int kc = kh * HD;

    float4 klo = *(const float4*)(part + rbase + kc + d4);
    float4 khi = *(const float4*)(part + rbase + kc + 64 + d4);
    float4 klo2 = *(const float4*)(part + pz + rbase + kc + d4);
    float4 khi2 = *(const float4*)(part + pz + rbase + kc + 64 + d4);
    klo.x += klo2.x; klo.y += klo2.y; klo.z += klo2.z; klo.w += klo2.w;
    khi.x += khi2.x; khi.y += khi2.y; khi.z += khi2.z; khi.w += khi2.w;
    float4 bl = *(const float4*)(bkb + kc + d4);
    float4 bh = *(const float4*)(bkb + kc + 64 + d4);
    klo.x += bl.x; klo.y += bl.y; klo.z += bl.z; klo.w += bl.w;
    khi.x += bh.x; khi.y += bh.y; khi.z += bh.z; khi.w += bh.w;

    float4 c1 = *(const float4*)(cosp + s * HD + d4);
    float4 s1 = *(const float4*)(sinp + s * HD + d4);
    float4 c2 = *(const float4*)(cosp + s * HD + 64 + d4);
    float4 s2 = *(const float4*)(sinp + s * HD + 64 + d4);

    float4 rlo, rhi;
    rlo.x = klo.x * c1.x - khi.x * s1.x;
    rlo.y = klo.y * c1.y - khi.y * s1.y;
    rlo.z = klo.z * c1.z - khi.z * s1.z;
    rlo.w = klo.w * c1.w - khi.w * s1.w;
    rhi.x = khi.x * c2.x + klo.x * s2.x;
    rhi.y = khi.y * c2.y + klo.y * s2.y;
    rhi.z = khi.z * c2.z + klo.z * s2.z;
    rhi.w = khi.w * c2.w + klo.w * s2.w;

    *(float4*)(Kout + (size_t)s * KVDIM + kc + d4) = rlo;
    *(float4*)(Kout + (size_t)s * KVDIM + kc + 64 + d4) = rhi;

    float4 vlo = *(const float4*)(part + rbase + 256 + kc + d4);
    float4 vhi = *(const float4*)(part + rbase + 256 + kc + 64 + d4);
    float4 vlo2 = *(const float4*)(part + pz + rbase + 256 + kc + d4);
    float4 vhi2 = *(const float4*)(part + pz + rbase + 256 + kc + 64 + d4);
    float4 vbl = *(const float4*)(bvb + kc + d4);
    float4 vbh = *(const float4*)(bvb + kc + 64 + d4);
    vlo.x += vlo2.x + vbl.x; vlo.y += vlo2.y + vbl.y;
    vlo.z += vlo2.z + vbl.z; vlo.w += vlo2.w + vbl.w;
    vhi.x += vhi2.x + vbh.x; vhi.y += vhi2.y + vbh.y;
    vhi.z += vhi2.z + vbh.z; vhi.w += vhi2.w + vbh.w;

    *(float4*)(Vout + (size_t)s * KVDIM + kc + d4) = vlo;
    *(float4*)(Vout + (size_t)s * KVDIM + kc + 64 + d4) = vhi;
}

// ---------------------------------------------------------------------------
// RoPE for Q (unchanged).
// ---------------------------------------------------------------------------
__global__ __launch_bounds__(256) void rope_q(
    float* __restrict__ x, const float* __restrict__ cosp,
    const float* __restrict__ sinp)
{
    int idx = blockIdx.x * blockDim.x + threadIdx.x;
    int d4 = (idx & 15) * 4;
    int hh = (idx >> 4) & 15;
    int s  = idx >> 8;
    if (s >= S_LEN) return;
    size_t b = (size_t)s * QDIM + hh * HD;

    float4 x1 = *(float4*)(x + b + d4);
    float4 x2 = *(float4*)(x + b + 64 + d4);
    float4 c1 = *(const float4*)(cosp + s * HD + d4);
    float4 s1 = *(const float4*)(sinp + s * HD + d4);
    float4 c2 = *(const float4*)(cosp + s * HD + 64 + d4);
    float4 s2 = *(const float4*)(sinp + s * HD + 64 + d4);

    float4 r1v, r2v;
    r1v.x = x1.x * c1.x - x2.x * s1.x;
    r1v.y = x1.y * c1.y - x2.y * s1.y;
    r1v.z = x1.z * c1.z - x2.z * s1.z;
    r1v.w = x1.w * c1.w - x2.w * s1.w;
    r2v.x = x2.x * c2.x + x1.x * s2.x;
    r2v.y = x2.y * c2.y + x1.y * s2.y;
    r2v.z = x2.z * c2.z + x1.z * s2.z;
    r2v.w = x2.w * c2.w + x1.w * s2.w;

    *(float4*)(x + b + d4) = r1v;
    *(float4*)(x + b + 64 + d4) = r2v;
}

// ===========================================================================
// Flash attention, tf32 mma.sync (unchanged from R4/R8).
// ===========================================================================
#define KS_STRIDE 132
#define PS_STRIDE 68
#define FA_SMEM ((2 * 64 * KS_STRIDE + 64 * PS_STRIDE) * 4)

__global__ __launch_bounds__(128) void flash_attn_tc(
    const float* __restrict__ Q, const float* __restrict__ Kp,
    const float* __restrict__ Vp, float* __restrict__ O)
{
    extern __shared__ float smf[];
    const uint32_t Ksb = smem_to_u32(smf);
    const uint32_t Vsb = Ksb + 64 * KS_STRIDE * 4;
    const uint32_t Psb = Vsb + 64 * KS_STRIDE * 4;

    const int qb = gridDim.x - 1 - blockIdx.x;
    const int h = blockIdx.y;
    const int kvh = h / NREP;
    const int tid = threadIdx.x;
    const int lane = tid & 31, wid = tid >> 5;
    const int r4 = lane >> 2, cc = lane & 3;
    const int q0 = qb * 64;
    const int m0 = wid * 16;
    const float scale = 0.08838834764831845f;

    uint32_t qfrag[16][4];
    {
        const float* qA = Q + (size_t)(q0 + m0 + r4) * QDIM + h * HD;
        const float* qB = qA + 8 * QDIM;
        #pragma unroll
        for (int kt = 0; kt < 16; kt++) {
            qfrag[kt][0] = f2tf32(qA[kt * 8 + cc]);
            qfrag[kt][1] = f2tf32(qB[kt * 8 + cc]);
            qfrag[kt][2] = f2tf32(qA[kt * 8 + cc + 4]);
            qfrag[kt][3] = f2tf32(qB[kt * 8 + cc + 4]);
        }
    }

    float mA = -1e30f, mB = -1e30f, lA = 0.f, lB = 0.f;
    float ofrag[16][4];
    #pragma unroll
    for (int nt = 0; nt < 16; nt++)
        #pragma unroll
        for (int j = 0; j < 4; j++) ofrag[nt][j] = 0.f;

    const int rgA = q0 + m0 + r4;
    const int rgB = rgA + 8;

    for (int kb = 0; kb <= qb; kb++) {
        const int k0 = kb * 64;
        __syncthreads();
        #pragma unroll
        for (int t = 0; t < 16; t++) {
            int i = tid + t * 128;
            int r = i >> 5, c4 = (i & 31) * 4;
            size_t goff = (size_t)(k0 + r) * KVDIM + kvh * HD + c4;
            float4 kv = *(const float4*)(Kp + goff);
            float4 vv = *(const float4*)(Vp + goff);
            uint32_t soff = (uint32_t)((r * KS_STRIDE + c4) * 4);
            sts128u(Ksb + soff, f2tf32(kv.x), f2tf32(kv.y), f2tf32(kv.z), f2tf32(kv.w));
            sts128u(Vsb + soff, f2tf32(vv.x), f2tf32(vv.y), f2tf32(vv.z), f2tf32(vv.w));
        }
        __syncthreads();

        float sfr[8][4];
        #pragma unroll
        for (int nt = 0; nt < 8; nt++)
            #pragma unroll
            for (int j = 0; j < 4; j++) sfr[nt][j] = 0.f;

        #pragma unroll
        for (int kt = 0; kt < 16; kt++) {
            uint32_t bfr[8][2];
            #pragma unroll
            for (int nt = 0; nt < 8; nt++) {
                uint32_t ba = Ksb + (uint32_t)((((nt * 8 + r4) * KS_STRIDE) + kt * 8 + cc) * 4);
                bfr[nt][0] = ldsu(ba);
                bfr[nt][1] = ldsu(ba + 16);
            }
            #pragma unroll
            for (int nt = 0; nt < 8; nt++)
                mma_tf32(sfr[nt], qfrag[kt], bfr[nt]);
        }

        const bool diag = (kb == qb);
        #pragma unroll
        for (int nt = 0; nt < 8; nt++) {
            int cg = k0 + nt * 8 + 2 * cc;
            sfr[nt][0] *= scale; sfr[nt][1] *= scale;
            sfr[nt][2] *= scale; sfr[nt][3] *= scale;
            if (diag) {
                if (cg     > rgA) sfr[nt][0] = -1e30f;
                if (cg + 1 > rgA) sfr[nt][1] = -1e30f;
                if (cg     > rgB) sfr[nt][2] = -1e30f;
                if (cg + 1 > rgB) sfr[nt][3] = -1e30f;
            }
        }

        float rmA = -1e30f, rmB = -1e30f;
        #pragma unroll
        for (int nt = 0; nt < 8; nt++) {
            rmA = fmaxf(rmA, fmaxf(sfr[nt][0], sfr[nt][1]));
            rmB = fmaxf(rmB, fmaxf(sfr[nt][2], sfr[nt][3]));
        }
        rmA = fmaxf(rmA, __shfl_xor_sync(0xffffffffu, rmA, 1));
        rmA = fmaxf(rmA, __shfl_xor_sync(0xffffffffu, rmA, 2));
        rmB = fmaxf(rmB, __shfl_xor_sync(0xffffffffu, rmB, 1));
        rmB = fmaxf(rmB, __shfl_xor_sync(0xffffffffu, rmB, 2));

        float mnA = fmaxf(mA, rmA), mnB = fmaxf(mB, rmB);
        float aA = __expf(mA - mnA), aB = __expf(mB - mnB);
        mA = mnA; mB = mnB;

        float smA = 0.f, smB = 0.f;
        #pragma unroll
        for (int nt = 0; nt < 8; nt++) {
            sfr[nt][0] = __expf(sfr[nt][0] - mnA);
            sfr[nt][1] = __expf(sfr[nt][1] - mnA);
            sfr[nt][2] = __expf(sfr[nt][2] - mnB);
            sfr[nt][3] = __expf(sfr[nt][3] - mnB);
            smA += sfr[nt][0] + sfr[nt][1];
            smB += sfr[nt][2] + sfr[nt][3];
        }
        smA += __shfl_xor_sync(0xffffffffu, smA, 1);
        smA += __shfl_xor_sync(0xffffffffu, smA, 2);
        smB += __shfl_xor_sync(0xffffffffu, smB, 1);
        smB += __shfl_xor_sync(0xffffffffu, smB, 2);
        lA = lA * aA + smA;
        lB = lB * aB + smB;

        #pragma unroll
        for (int nt = 0; nt < 16; nt++) {
            ofrag[nt][0] *= aA; ofrag[nt][1] *= aA;
            ofrag[nt][2] *= aB; ofrag[nt][3] *= aB;
        }

        #pragma unroll
        for (int nt = 0; nt < 8; nt++) {
            uint32_t pa0 = Psb + (uint32_t)((((m0 + r4) * PS_STRIDE) + nt * 8 + 2 * cc) * 4);
            sts64u(pa0, f2tf32(sfr[nt][0]), f2tf32(sfr[nt][1]));
            sts64u(pa0 + 8 * PS_STRIDE * 4, f2tf32(sfr[nt][2]), f2tf32(sfr[nt][3]));
        }
        __syncwarp();

        #pragma unroll
        for (int kt = 0; kt < 8; kt++) {
            uint32_t afr[4];
            uint32_t pb = Psb + (uint32_t)((((m0 + r4) * PS_STRIDE) + kt * 8 + cc) * 4);
            afr[0] = ldsu(pb);
            afr[1] = ldsu(pb + 8 * PS_STRIDE * 4);
            afr[2] = ldsu(pb + 16);
            afr[3] = ldsu(pb + 8 * PS_STRIDE * 4 + 16);
            #pragma unroll
            for (int nt = 0; nt < 16; nt++) {
                uint32_t vb = Vsb + (uint32_t)((((kt * 8 + cc) * KS_STRIDE) + nt * 8 + r4) * 4);
                uint32_t b0 = ldsu(vb);
                uint32_t b1 = ldsu(vb + 4 * KS_STRIDE * 4);
                uint32_t bfr[2] = { b0, b1 };
                mma_tf32(ofrag[nt], afr, bfr);
            }
        }
    }

    const float iA = 1.f / lA, iB = 1.f / lB;
    #pragma unroll
    for (int nt = 0; nt < 16; nt++) {
        int col = h * HD + nt * 8 + 2 * cc;
        float2 vA, vB;
        vA.x = ofrag[nt][0] * iA; vA.y = ofrag[nt][1] * iA;
        vB.x = ofrag[nt][2] * iB; vB.y = ofrag[nt][3] * iB;
        *(float2*)(O + (size_t)rgA * QDIM + col) = vA;
        *(float2*)(O + (size_t)rgB * QDIM + col) = vB;
    }
}

// ---------------------------------------------------------------------------
extern "C" void kernel_launch(void* const* d_in, const int* in_sizes, int n_in,
                              void* d_out, int out_size)
{
    const float* X    = (const float*)d_in[0];
    const float* cosp = (const float*)d_in[1];
    const float* sinp = (const float*)d_in[2];
    // d_in[3] = attention_mask (causal by construction; applied analytically)
    const float* Wq = (const float*)d_in[4];
    const float* bq = (const float*)d_in[5];
    const float* Wk = (const float*)d_in[6];
    const float* bk = (const float*)d_in[7];
    const float* Wv = (const float*)d_in[8];
    const float* bv = (const float*)d_in[9];
    const float* Wo = (const float*)d_in[10];
    float* out = (float*)d_out;

    float *q, *k, *v, *att, *part;
    cudaGetSymbolAddress((void**)&q, g_q);
    cudaGetSymbolAddress((void**)&k, g_k);
    cudaGetSymbolAddress((void**)&v, g_v);
    cudaGetSymbolAddress((void**)&att, g_att);
    cudaGetSymbolAddress((void**)&part, g_part);

    cudaFuncSetAttribute(tcgemm_big, cudaFuncAttributeMaxDynamicSharedMemorySize, GEMM2_SMEM);
    cudaFuncSetAttribute(kv_gemm_tf32, cudaFuncAttributeMaxDynamicSharedMemorySize, GEMM_SMEM);
    cudaFuncSetAttribute(flash_attn_tc, cudaFuncAttributeMaxDynamicSharedMemorySize, FA_SMEM);

    // Q projection (256x128-tile tf32 mma.sync, cp.async pipeline)
    tcgemm_big<<<dim3(QDIM / 128, S_LEN / 256), 256, GEMM2_SMEM>>>(X, Wq, bq, q, QDIM, HIDDEN);

    // Fused K+V projection, split-K=2 -> partials
    kv_gemm_tf32<<<dim3(4, S_LEN / 128, 2), 256, GEMM_SMEM>>>(X, Wk, Wv, part);

    // Reduce + bias + RoPE(K) -> g_k, g_v
    kv_finish<<<(S_LEN * 2 * 16 + 255) / 256, 256>>>(part, bk, bv, cosp, sinp, k, v);

    // RoPE on Q (vectorized)
    rope_q<<<(S_LEN * 16 * 16 + 255) / 256, 256>>>(q, cosp, sinp);

    // Flash attention (tf32 mma.sync)
    flash_attn_tc<<<dim3(S_LEN / 64, NH), 128, FA_SMEM>>>(q, k, v, att);

    // Output projection (256x128-tile tf32 mma.sync, cp.async) -> d_out
    tcgemm_big<<<dim3(QDIM / 128, S_LEN / 256), 256, GEMM2_SMEM>>>(att, Wo, nullptr, out, QDIM, HIDDEN);
}